// round 12
// baseline (speedup 1.0000x reference)
#include <cuda_runtime.h>
#include <cuda_bf16.h>
#include <cstdint>

// ---------------- problem constants ----------------
#define NIMG 2048          // T*B
#define TSTEPS 64
#define BBATCH 32
#define HID 128

// ---------------- device scratch -------------------
__device__ float g_c1[NIMG * 400 * 32];    // conv1 out [n][20*20][32]
__device__ float g_c2[NIMG * 81 * 64];     // conv2 out [n][9*9][64]
__device__ float g_c3[NIMG * 3136];        // conv3 out [n][49*64]
__device__ float g_feat[NIMG * 512];       // fc out
__device__ float g_xw[NIMG * 512];         // x@Wih^T + biases + one-hot
__device__ float g_hT[2][HID * BBATCH];
__device__ float g_hs[NIMG * HID];
__device__ unsigned g_bar;

// bf16 hi/lo split weights, transposed to [N][K]
__device__ __nv_bfloat16 g_WfcT_h[512 * 3136];
__device__ __nv_bfloat16 g_WfcT_l[512 * 3136];
__device__ __nv_bfloat16 g_W2T_h[64 * 512];
__device__ __nv_bfloat16 g_W2T_l[64 * 512];
__device__ __nv_bfloat16 g_W3T_h[64 * 576];
__device__ __nv_bfloat16 g_W3T_l[64 * 576];

__global__ void init_kernel() {
    if (threadIdx.x == 0) g_bar = 0u;
}

// ---------------- packed f32x2 helpers ----------------
__device__ __forceinline__ void fma2(unsigned long long& d,
                                     unsigned long long a,
                                     unsigned long long b) {
    asm("fma.rn.f32x2 %0, %1, %2, %3;" : "=l"(d) : "l"(a), "l"(b), "l"(d));
}
__device__ __forceinline__ unsigned long long pack2(float lo, float hi) {
    unsigned long long r;
    asm("mov.b64 %0, {%1, %2};" : "=l"(r) : "f"(lo), "f"(hi));
    return r;
}
__device__ __forceinline__ float2 unpack2(unsigned long long v) {
    float2 r;
    asm("mov.b64 {%0, %1}, %2;" : "=f"(r.x), "=f"(r.y) : "l"(v));
    return r;
}

// ---------------- warp MMA helpers (base-ISA, not 'a'-gated) ----------------
__device__ __forceinline__ uint32_t smem_u32(const void* p) {
    uint32_t a;
    asm("{ .reg .u64 t; cvta.to.shared.u64 t, %1; cvt.u32.u64 %0, t; }"
        : "=r"(a) : "l"(p));
    return a;
}
__device__ __forceinline__ void mma16816(float* c, const uint32_t* a, const uint32_t* b) {
    asm volatile(
        "mma.sync.aligned.m16n8k16.row.col.f32.bf16.bf16.f32 "
        "{%0,%1,%2,%3}, {%4,%5,%6,%7}, {%8,%9}, {%0,%1,%2,%3};"
        : "+f"(c[0]), "+f"(c[1]), "+f"(c[2]), "+f"(c[3])
        : "r"(a[0]), "r"(a[1]), "r"(a[2]), "r"(a[3]), "r"(b[0]), "r"(b[1]));
}
__device__ __forceinline__ void ldsm_x4(uint32_t* r, uint32_t addr) {
    asm volatile("ldmatrix.sync.aligned.m8n8.x4.shared.b16 {%0,%1,%2,%3}, [%4];"
                 : "=r"(r[0]), "=r"(r[1]), "=r"(r[2]), "=r"(r[3]) : "r"(addr));
}
__device__ __forceinline__ void ldsm_x2(uint32_t* r, uint32_t addr) {
    asm volatile("ldmatrix.sync.aligned.m8n8.x2.shared.b16 {%0,%1}, [%2];"
                 : "=r"(r[0]), "=r"(r[1]) : "r"(addr));
}

// ---------------- weight pre-transpose + bf16 hi/lo split -----------------
template<int K, int N>
__device__ __forceinline__ void wsplit_body(const float* __restrict__ W,
                                            __nv_bfloat16* __restrict__ Th,
                                            __nv_bfloat16* __restrict__ Tl) {
    int total = K * N;
    for (int idx = blockIdx.x * blockDim.x + threadIdx.x; idx < total;
         idx += gridDim.x * blockDim.x) {
        int n = idx / K, k = idx - n * K;
        float x = __ldg(&W[(size_t)k * N + n]);
        __nv_bfloat16 h = __float2bfloat16(x);
        float r = x - __bfloat162float(h);
        Th[idx] = h;
        Tl[idx] = __float2bfloat16(r);
    }
}
__global__ void wsplit_fc_kernel(const float* __restrict__ W) {
    wsplit_body<3136, 512>(W, g_WfcT_h, g_WfcT_l);
}
__global__ void wsplit_c2_kernel(const float* __restrict__ W) {
    wsplit_body<512, 64>(W, g_W2T_h, g_W2T_l);
}
__global__ void wsplit_c3_kernel(const float* __restrict__ W) {
    wsplit_body<576, 64>(W, g_W3T_h, g_W3T_l);
}

// ============ HMMA bf16x3 GEMM: C = relu(A*B^T + bias) ============
// A[M,K] fp32 (optionally im2col), B^T bf16 hi/lo [N][K].
// CTA: 128(M) x 64(N); 8 warps as 4(M) x 2(N); warptile 32x32 =
// 2 m16-tiles x 4 n8-tiles, m16n8k16 mma, 3 split terms.
// Smem rows padded to 72 bf16 (144B) -> ldmatrix conflict-free.
template<int NTOT, int K, int IM2COL, int P, int PW, int S, int IW, int CI, int KW>
__device__ void mgemm_body(const float* __restrict__ Afp,
                           const __nv_bfloat16* __restrict__ BhT,
                           const __nv_bfloat16* __restrict__ BlT,
                           const float* __restrict__ bias,
                           float* __restrict__ outp)
{
    extern __shared__ char smem[];
    constexpr int LDA = 72;                       // bf16 per smem row
    constexpr int A_BYTES = 128 * LDA * 2;        // 18432
    constexpr int B_BYTES = 64 * LDA * 2;         // 9216
    constexpr int OFF_AH  = 0;
    constexpr int OFF_AL  = A_BYTES;
    constexpr int OFF_BH  = 2 * A_BYTES;
    constexpr int OFF_BL  = 2 * A_BYTES + B_BYTES;
    constexpr int OFF_KO  = 2 * A_BYTES + 2 * B_BYTES;
    constexpr int OFF_ROW = OFF_KO + (IM2COL ? K * 4 : 0);

    const int t = threadIdx.x;
    const int wid = t >> 5, L = t & 31;
    const int wm = wid >> 1, wn = wid & 1;
    const int g = L >> 2, tc = L & 3;
    const int bm = blockIdx.y * 128;
    const int bn = blockIdx.x * 64;
    uint32_t sbase = smem_u32(smem);
    int* s_koff = (int*)(smem + OFF_KO);
    int* s_row  = (int*)(smem + OFF_ROW);

    if (IM2COL) {
        for (int i = t; i < K; i += 256) {
            int ky = i / (KW * CI);
            int r  = i - ky * (KW * CI);
            int kx = r / CI;
            int ci = r - kx * CI;
            s_koff[i] = (ky * IW + kx) * CI + ci;
        }
        if (t < 128) {
            int m = bm + t;
            int n = m / P;
            int p = m - n * P;
            int py = p / PW;
            int px = p - py * PW;
            s_row[t] = n * (IW * IW * CI) + (py * S * IW + px * S) * CI;
        }
        __syncthreads();
    }

    // per-lane ldmatrix base addresses (bytes)
    const uint32_t aoffL = (uint32_t)((wm * 32 + (L & 15)) * (LDA * 2) + (L >> 4) * 16);
    const uint32_t boffL = (uint32_t)((wn * 32 + (L & 7)) * (LDA * 2) + ((L >> 3) & 1) * 16);
    const uint32_t aH = sbase + OFF_AH + aoffL;
    const uint32_t aL = sbase + OFF_AL + aoffL;
    const uint32_t bH = sbase + OFF_BH + boffL;
    const uint32_t bL = sbase + OFF_BL + boffL;

    float acc[2][4][4];
#pragma unroll
    for (int i = 0; i < 2; i++)
#pragma unroll
        for (int j = 0; j < 4; j++)
#pragma unroll
            for (int q = 0; q < 4; q++) acc[i][j][q] = 0.f;

    constexpr int NCH = K / 64;
    for (int ch = 0; ch < NCH; ch++) {
        const int k0 = ch * 64;
        // ---- stage A: 128x64 fp32 -> bf16 hi/lo ----
        for (int e = t; e < 128 * 64; e += 256) {
            int r = e >> 6, c = e & 63;
            size_t aoff;
            if (IM2COL) aoff = (size_t)(s_row[r] + s_koff[k0 + c]);
            else        aoff = (size_t)(bm + r) * K + k0 + c;
            float x = __ldg(&Afp[aoff]);
            __nv_bfloat16 h = __float2bfloat16(x);
            __nv_bfloat16 l = __float2bfloat16(x - __bfloat162float(h));
            int bo = r * (LDA * 2) + c * 2;
            *(__nv_bfloat16*)(smem + OFF_AH + bo) = h;
            *(__nv_bfloat16*)(smem + OFF_AL + bo) = l;
        }
        // ---- stage B: 64x64 bf16 hi/lo as 32-bit words ----
        for (int e = t; e < 64 * 32; e += 256) {
            int n = e >> 5, wq = e & 31;
            size_t srcw = ((size_t)(bn + n) * K + k0) / 2 + wq;
            uint32_t vh = ((const uint32_t*)BhT)[srcw];
            uint32_t vl = ((const uint32_t*)BlT)[srcw];
            ((uint32_t*)(smem + OFF_BH))[n * (LDA / 2) + wq] = vh;
            ((uint32_t*)(smem + OFF_BL))[n * (LDA / 2) + wq] = vl;
        }
        __syncthreads();

#pragma unroll
        for (int ks = 0; ks < 4; ks++) {
            uint32_t ah[2][4], al[2][4], bh[4][2], bl[4][2];
#pragma unroll
            for (int mt = 0; mt < 2; mt++) {
                ldsm_x4(ah[mt], aH + mt * 16 * (LDA * 2) + ks * 32);
                ldsm_x4(al[mt], aL + mt * 16 * (LDA * 2) + ks * 32);
            }
#pragma unroll
            for (int nt = 0; nt < 4; nt++) {
                ldsm_x2(bh[nt], bH + nt * 8 * (LDA * 2) + ks * 32);
                ldsm_x2(bl[nt], bL + nt * 8 * (LDA * 2) + ks * 32);
            }
#pragma unroll
            for (int mt = 0; mt < 2; mt++)
#pragma unroll
                for (int nt = 0; nt < 4; nt++) {
                    mma16816(acc[mt][nt], ah[mt], bh[nt]);
                    mma16816(acc[mt][nt], ah[mt], bl[nt]);
                    mma16816(acc[mt][nt], al[mt], bh[nt]);
                }
        }
        __syncthreads();
    }

    // ---- epilogue: c-frag layout -> gmem, bias + relu ----
#pragma unroll
    for (int mt = 0; mt < 2; mt++) {
#pragma unroll
        for (int nt = 0; nt < 4; nt++) {
            int col = bn + wn * 32 + nt * 8 + tc * 2;
            float b0 = __ldg(&bias[col]);
            float b1 = __ldg(&bias[col + 1]);
            int r0 = bm + wm * 32 + mt * 16 + g;
            float2 v0, v1;
            v0.x = fmaxf(acc[mt][nt][0] + b0, 0.f);
            v0.y = fmaxf(acc[mt][nt][1] + b1, 0.f);
            v1.x = fmaxf(acc[mt][nt][2] + b0, 0.f);
            v1.y = fmaxf(acc[mt][nt][3] + b1, 0.f);
            *(float2*)&outp[(size_t)r0 * NTOT + col]       = v0;
            *(float2*)&outp[(size_t)(r0 + 8) * NTOT + col] = v1;
        }
    }
}

// conv2: A = im2col(g_c1), M=165888, K=512, N=64
__global__ void __launch_bounds__(256) conv2m_kernel(const float* __restrict__ bias) {
    mgemm_body<64, 512, 1, 81, 9, 2, 20, 32, 4>(g_c1, g_W2T_h, g_W2T_l, bias, g_c2);
}
// conv3: A = im2col(g_c2), M=100352, K=576, N=64
__global__ void __launch_bounds__(256) conv3m_kernel(const float* __restrict__ bias) {
    mgemm_body<64, 576, 1, 49, 7, 1, 9, 64, 3>(g_c2, g_W3T_h, g_W3T_l, bias, g_c3);
}
// fc: A = g_c3, M=2048, K=3136, N=512
__global__ void __launch_bounds__(256) fcm_kernel(const float* __restrict__ bias) {
    mgemm_body<512, 3136, 0, 1, 1, 1, 1, 1, 1>(g_c3, g_WfcT_h, g_WfcT_l, bias, g_feat);
}

// ================= scalar implicit-GEMM conv (conv1 only) =================
template<int P, int PW, int S, int IW, int CI, int OC, int K, int KW, int BM>
__device__ __forceinline__ void convgemm_body(
    const float* __restrict__ in, const float* __restrict__ Wt,
    const float* __restrict__ bias, float* __restrict__ out)
{
    constexpr int IMGSZ = IW * IW * CI;
    constexpr int AS  = (BM == 128) ? 136 : 260;
    constexpr int BSS = OC + 4;
    constexpr int TN  = OC / 4;
    constexpr int LA  = BM / 16;
    constexpr int NIT = K / 16;

    __shared__ int s_koff[K];
    __shared__ __align__(16) float As[16][AS];
    __shared__ __align__(16) float Bs[16][BSS];

    const int t  = threadIdx.x;
    const int m0 = blockIdx.x * BM;

    for (int i = t; i < K; i += 256) {
        int ky = i / (KW * CI);
        int r  = i - ky * (KW * CI);
        int kx = r / CI;
        int ci = r - kx * CI;
        s_koff[i] = (ky * IW + kx) * CI + ci;
    }
    int rowoff[LA];
#pragma unroll
    for (int l = 0; l < LA; l++) {
        int m  = m0 + (t >> 4) + 16 * l;
        int n  = m / P;
        int p  = m - n * P;
        int py = p / PW;
        int px = p - py * PW;
        rowoff[l] = n * IMGSZ + (py * S * IW + px * S) * CI;
    }
    __syncthreads();

    const int tm  = t / TN;
    const int tn  = t - tm * TN;
    const int kkA = t & 15;
    const int mrA = t >> 4;
    const int brn = (OC == 64) ? (t >> 4) : (t >> 3);
    const int bcn = (OC == 64) ? ((t & 15) * 4) : ((t & 7) * 4);
    const bool bact = (OC == 64) || (t < 128);

    float  aReg[LA];
    float4 bReg;
    auto load_tile = [&](int k0) {
        int kof = s_koff[k0 + kkA];
#pragma unroll
        for (int l = 0; l < LA; l++)
            aReg[l] = __ldg(&in[(size_t)rowoff[l] + kof]);
        if (bact)
            bReg = *(const float4*)&Wt[(size_t)(k0 + brn) * OC + bcn];
    };
    auto store_tile = [&]() {
#pragma unroll
        for (int l = 0; l < LA; l++)
            As[kkA][mrA + 16 * l] = aReg[l];
        if (bact)
            *(float4*)&Bs[brn][bcn] = bReg;
    };

    unsigned long long acc2[4][4];
#pragma unroll
    for (int i = 0; i < 4; i++)
#pragma unroll
        for (int j = 0; j < 4; j++) acc2[i][j] = 0ull;

    load_tile(0);
    store_tile();
    __syncthreads();

    for (int it = 1; it <= NIT; it++) {
        if (it < NIT) load_tile(it * 16);
#pragma unroll
        for (int kk = 0; kk < 16; kk++) {
            const unsigned long long* ap =
                reinterpret_cast<const unsigned long long*>(&As[kk][tm * 8]);
            unsigned long long a2[4] = {ap[0], ap[1], ap[2], ap[3]};
            float4 bq = *(const float4*)&Bs[kk][tn * 4];
            unsigned long long b2[4] = {pack2(bq.x, bq.x), pack2(bq.y, bq.y),
                                        pack2(bq.z, bq.z), pack2(bq.w, bq.w)};
#pragma unroll
            for (int i = 0; i < 4; i++)
#pragma unroll
                for (int j = 0; j < 4; j++)
                    fma2(acc2[i][j], a2[i], b2[j]);
        }
        if (it < NIT) {
            __syncthreads();
            store_tile();
            __syncthreads();
        }
    }

    float4 bv = *(const float4*)&bias[tn * 4];
    float bb[4] = {bv.x, bv.y, bv.z, bv.w};
#pragma unroll
    for (int i2 = 0; i2 < 4; i2++) {
        int mlo = m0 + tm * 8 + 2 * i2;
        float2 u0 = unpack2(acc2[i2][0]);
        float2 u1 = unpack2(acc2[i2][1]);
        float2 u2 = unpack2(acc2[i2][2]);
        float2 u3 = unpack2(acc2[i2][3]);
        float4 olo, ohi;
        olo.x = fmaxf(u0.x + bb[0], 0.f);  ohi.x = fmaxf(u0.y + bb[0], 0.f);
        olo.y = fmaxf(u1.x + bb[1], 0.f);  ohi.y = fmaxf(u1.y + bb[1], 0.f);
        olo.z = fmaxf(u2.x + bb[2], 0.f);  ohi.z = fmaxf(u2.y + bb[2], 0.f);
        olo.w = fmaxf(u3.x + bb[3], 0.f);  ohi.w = fmaxf(u3.y + bb[3], 0.f);
        *(float4*)&out[(size_t)mlo * OC + tn * 4]       = olo;
        *(float4*)&out[(size_t)(mlo + 1) * OC + tn * 4] = ohi;
    }
}

__global__ void __launch_bounds__(256) conv1g_kernel(
    const float* __restrict__ img, const float* __restrict__ W,
    const float* __restrict__ bias)
{
    convgemm_body<400, 20, 4, 84, 3, 32, 192, 8, 256>(img, W, bias, g_c1);
}

// ---------------- xw: SGEMM 64x64x16 f32x2 (EPI: biases + one-hot) --------
__device__ __forceinline__ void xw_body(
    const float* __restrict__ A, const float* __restrict__ B,
    float* __restrict__ C, int N, int K, int ldb,
    const float* __restrict__ bias1, const float* __restrict__ bias2,
    const float* __restrict__ WihFull, const int* __restrict__ pos)
{
    __shared__ __align__(16) float As[16][68];
    __shared__ __align__(16) float Bs[16][68];
    int bm = blockIdx.y * 64, bn = blockIdx.x * 64;
    int t = threadIdx.x;
    int tm = t >> 4, tn = t & 15;

    unsigned long long acc2[2][4];
#pragma unroll
    for (int i = 0; i < 2; i++)
#pragma unroll
        for (int j = 0; j < 4; j++) acc2[i][j] = 0ull;

    int ar = t >> 2, ac = (t & 3) * 4;

    float4 avR, bvR;
    auto load_tile = [&](int k0) {
        avR = *(const float4*)(A + (size_t)(bm + ar) * K + k0 + ac);
        bvR = *(const float4*)(B + (size_t)(bn + ar) * ldb + k0 + ac);
    };
    auto store_tile = [&]() {
        As[ac + 0][ar] = avR.x; As[ac + 1][ar] = avR.y;
        As[ac + 2][ar] = avR.z; As[ac + 3][ar] = avR.w;
        Bs[ac + 0][ar] = bvR.x; Bs[ac + 1][ar] = bvR.y;
        Bs[ac + 2][ar] = bvR.z; Bs[ac + 3][ar] = bvR.w;
    };

    const int NIT = K / 16;
    load_tile(0);
    store_tile();
    __syncthreads();

    for (int it = 1; it <= NIT; it++) {
        if (it < NIT) load_tile(it * 16);
#pragma unroll
        for (int kk = 0; kk < 16; kk++) {
            const unsigned long long* ap =
                reinterpret_cast<const unsigned long long*>(&As[kk][tm * 4]);
            unsigned long long a2[2] = {ap[0], ap[1]};
            float4 bq = *(const float4*)&Bs[kk][tn * 4];
            unsigned long long b2[4] = {pack2(bq.x, bq.x), pack2(bq.y, bq.y),
                                        pack2(bq.z, bq.z), pack2(bq.w, bq.w)};
#pragma unroll
            for (int i = 0; i < 2; i++)
#pragma unroll
                for (int j = 0; j < 4; j++)
                    fma2(acc2[i][j], a2[i], b2[j]);
        }
        if (it < NIT) {
            __syncthreads();
            store_tile();
            __syncthreads();
        }
    }
#pragma unroll
    for (int i2 = 0; i2 < 2; i2++) {
        float2 u[4];
#pragma unroll
        for (int j = 0; j < 4; j++) u[j] = unpack2(acc2[i2][j]);
#pragma unroll
        for (int half = 0; half < 2; half++) {
            int row = bm + tm * 4 + 2 * i2 + half;
            int p0 = pos[2 * row], p1 = pos[2 * row + 1];
#pragma unroll
            for (int j = 0; j < 4; j++) {
                int col = bn + tn * 4 + j;
                float v = half ? u[j].y : u[j].x;
                v += bias1[col] + bias2[col]
                   + WihFull[(size_t)col * 532 + 512 + p0]
                   + WihFull[(size_t)col * 532 + 522 + p1];
                C[(size_t)row * N + col] = v;
            }
        }
    }
}

__global__ void __launch_bounds__(256) xw_kernel(
    const float* __restrict__ Wih, const float* __restrict__ bih,
    const float* __restrict__ bhh, const int* __restrict__ pos)
{
    xw_body(g_feat, Wih, g_xw, 512, 512, 532, bih, bhh, Wih, pos);
}

// ---------------- persistent LSTM: 32 blocks x 128 threads --------------
__device__ __forceinline__ float sigmoidf_(float x) {
    return 1.0f / (1.0f + __expf(-x));
}

__global__ void __launch_bounds__(128) lstm_kernel(
    const int* __restrict__ done, const float* __restrict__ h0,
    const float* __restrict__ c0, const float* __restrict__ Whh,
    float* __restrict__ out)
{
    int k = blockIdx.x;
    int t = threadIdx.x;
    int lane = t & 31, w = t >> 5;

    __shared__ float whh_s[16][HID];
    __shared__ float h_sh[HID][BBATCH];
    __shared__ float c_s[4][BBATCH];
    __shared__ float gate_s[4][4][BBATCH];
    __shared__ float m_s[BBATCH];

    for (int idx = t; idx < 16 * HID; idx += 128) {
        int r = idx >> 7, j = idx & 127;
        int G = (r >> 2) * HID + k * 4 + (r & 3);
        whh_s[r][j] = Whh[(size_t)G * HID + j];
    }
    c_s[w][lane] = c0[lane * HID + k * 4 + w];
    __stcg(&g_hT[0][(k * 4 + w) * BBATCH + lane], h0[lane * HID + k * 4 + w]);
    __threadfence();
    __syncthreads();
    unsigned target = 32;
    if (t == 0) {
        atomicAdd(&g_bar, 1u);
        while (*((volatile unsigned*)&g_bar) < target) {}
    }
    __syncthreads();

    float h_last = 0.f;
    for (int step = 0; step < TSTEPS; step++) {
        int p = step & 1;
        if (t < 32) m_s[t] = 1.0f - (float)done[step * BBATCH + t];
        __syncthreads();
        for (int idx = t; idx < HID * BBATCH; idx += 128) {
            h_sh[idx >> 5][idx & 31] = __ldcg(&g_hT[p][idx]) * m_s[idx & 31];
        }
        __syncthreads();

        float acc[4];
        const float* xwr = g_xw + (size_t)(step * BBATCH + lane) * 512 + w * HID + k * 4;
#pragma unroll
        for (int ul = 0; ul < 4; ul++) acc[ul] = xwr[ul];
#pragma unroll 4
        for (int j = 0; j < HID; j++) {
            float hv = h_sh[j][lane];
#pragma unroll
            for (int ul = 0; ul < 4; ul++) acc[ul] += hv * whh_s[w * 4 + ul][j];
        }
#pragma unroll
        for (int ul = 0; ul < 4; ul++) gate_s[w][ul][lane] = acc[ul];
        __syncthreads();

        float iv = sigmoidf_(gate_s[0][w][lane]);
        float fv = sigmoidf_(gate_s[1][w][lane]);
        float gv = tanhf(gate_s[2][w][lane]);
        float ov = sigmoidf_(gate_s[3][w][lane]);
        float cc = fv * (c_s[w][lane] * m_s[lane]) + iv * gv;
        c_s[w][lane] = cc;
        float hh = ov * tanhf(cc);
        h_last = hh;
        __stcg(&g_hT[1 - p][(k * 4 + w) * BBATCH + lane], hh);
        g_hs[(size_t)(step * BBATCH + lane) * HID + k * 4 + w] = hh;
        __threadfence();
        __syncthreads();
        target += 32;
        if (t == 0) {
            atomicAdd(&g_bar, 1u);
            while (*((volatile unsigned*)&g_bar) < target) {}
        }
        __syncthreads();
    }
    out[12288 + lane * HID + k * 4 + w] = h_last;
    out[16384 + lane * HID + k * 4 + w] = c_s[w][lane];
}

// ---------------- heads: logits (2048x5) + value (2048x1) ---------------
__global__ void heads_kernel(
    const float* __restrict__ Wp, const float* __restrict__ bp,
    const float* __restrict__ Wv, const float* __restrict__ bv,
    float* __restrict__ out)
{
    int row = blockIdx.x * 8 + threadIdx.y;
    int lane = threadIdx.x;
    const float* h = g_hs + (size_t)row * HID;
    float4 hv = *(const float4*)&h[lane * 4];
    float vals[4] = {hv.x, hv.y, hv.z, hv.w};
    float r[6];
#pragma unroll
    for (int a = 0; a < 5; a++) {
        float s = 0.f;
#pragma unroll
        for (int q = 0; q < 4; q++) s += vals[q] * __ldg(&Wp[(lane * 4 + q) * 5 + a]);
        r[a] = s;
    }
    {
        float s = 0.f;
#pragma unroll
        for (int q = 0; q < 4; q++) s += vals[q] * __ldg(&Wv[lane * 4 + q]);
        r[5] = s;
    }
#pragma unroll
    for (int a = 0; a < 6; a++)
#pragma unroll
        for (int off = 16; off > 0; off >>= 1)
            r[a] += __shfl_xor_sync(0xffffffffu, r[a], off);
    if (lane == 0) {
#pragma unroll
        for (int a = 0; a < 5; a++) out[(size_t)row * 5 + a] = r[a] + __ldg(&bp[a]);
        out[10240 + row] = r[5] + __ldg(&bv[0]);
    }
}

// ---------------- launch ----------------
extern "C" void kernel_launch(void* const* d_in, const int* in_sizes, int n_in,
                              void* d_out, int out_size)
{
    const float* image    = (const float*)d_in[0];
    const int*   position = (const int*)d_in[1];
    const int*   done     = (const int*)d_in[2];
    const float* h0       = (const float*)d_in[3];
    const float* c0       = (const float*)d_in[4];
    const float* W1  = (const float*)d_in[5];
    const float* b1  = (const float*)d_in[6];
    const float* W2  = (const float*)d_in[7];
    const float* b2  = (const float*)d_in[8];
    const float* W3  = (const float*)d_in[9];
    const float* b3  = (const float*)d_in[10];
    const float* Wfc = (const float*)d_in[11];
    const float* bfc = (const float*)d_in[12];
    const float* Wih = (const float*)d_in[13];
    const float* Whh = (const float*)d_in[14];
    const float* bih = (const float*)d_in[15];
    const float* bhh = (const float*)d_in[16];
    const float* Wp  = (const float*)d_in[17];
    const float* bp  = (const float*)d_in[18];
    const float* Wv  = (const float*)d_in[19];
    const float* bv  = (const float*)d_in[20];
    float* out = (float*)d_out;

    // dynamic smem: 2*18432 (A hi/lo) + 2*9216 (B hi/lo) + tables
    const int SM_C2 = 55296 + 512 * 4 + 512;   // 58112 - K=512 koff + 128 rows
    const int SM_C3 = 55296 + 576 * 4 + 512;   // 58112
    const int SM_FC = 55296;
    cudaFuncSetAttribute(conv2m_kernel, cudaFuncAttributeMaxDynamicSharedMemorySize, SM_C2);
    cudaFuncSetAttribute(conv3m_kernel, cudaFuncAttributeMaxDynamicSharedMemorySize, SM_C3);
    cudaFuncSetAttribute(fcm_kernel,   cudaFuncAttributeMaxDynamicSharedMemorySize, SM_FC);

    init_kernel<<<1, 32>>>();
    wsplit_fc_kernel<<<512, 256>>>(Wfc);
    wsplit_c2_kernel<<<32, 256>>>(W2);
    wsplit_c3_kernel<<<32, 256>>>(W3);
    conv1g_kernel<<<819200 / 256, 256>>>(image, W1, b1);
    conv2m_kernel<<<dim3(1, 165888 / 128), 256, SM_C2>>>(b2);
    conv3m_kernel<<<dim3(1, 100352 / 128), 256, SM_C3>>>(b3);
    fcm_kernel<<<dim3(8, 2048 / 128), 256, SM_FC>>>(bfc);
    xw_kernel<<<dim3(8, 32), 256>>>(Wih, bih, bhh, position);
    lstm_kernel<<<32, 128>>>(done, h0, c0, Whh, out);
    heads_kernel<<<256, dim3(32, 8)>>>(Wp, bp, Wv, bv, out);
}

// round 13
// speedup vs baseline: 1.3106x; 1.3106x over previous
#include <cuda_runtime.h>
#include <cuda_bf16.h>
#include <cstdint>

// ---------------- problem constants ----------------
#define NIMG 2048          // T*B
#define TSTEPS 64
#define BBATCH 32
#define HID 128

// ---------------- device scratch -------------------
// activations stored as bf16 hi/lo split pairs [m][k]
__device__ __nv_bfloat16 g_c1h[NIMG * 400 * 32];
__device__ __nv_bfloat16 g_c1l[NIMG * 400 * 32];
__device__ __nv_bfloat16 g_c2h[NIMG * 81 * 64];
__device__ __nv_bfloat16 g_c2l[NIMG * 81 * 64];
__device__ __nv_bfloat16 g_c3h[NIMG * 3136];
__device__ __nv_bfloat16 g_c3l[NIMG * 3136];
__device__ float g_feat[NIMG * 512];       // fc out (fp32)
__device__ float g_xw[NIMG * 512];         // x@Wih^T + biases + one-hot
__device__ float g_hT[2][HID * BBATCH];
__device__ float g_hs[NIMG * HID];
__device__ unsigned g_bar;

// bf16 hi/lo split weights, transposed to [N][K]
__device__ __nv_bfloat16 g_WfcT_h[512 * 3136];
__device__ __nv_bfloat16 g_WfcT_l[512 * 3136];
__device__ __nv_bfloat16 g_W2T_h[64 * 512];
__device__ __nv_bfloat16 g_W2T_l[64 * 512];
__device__ __nv_bfloat16 g_W3T_h[64 * 576];
__device__ __nv_bfloat16 g_W3T_l[64 * 576];

__global__ void init_kernel() {
    if (threadIdx.x == 0) g_bar = 0u;
}

// ---------------- packed f32x2 helpers ----------------
__device__ __forceinline__ void fma2(unsigned long long& d,
                                     unsigned long long a,
                                     unsigned long long b) {
    asm("fma.rn.f32x2 %0, %1, %2, %3;" : "=l"(d) : "l"(a), "l"(b), "l"(d));
}
__device__ __forceinline__ unsigned long long pack2(float lo, float hi) {
    unsigned long long r;
    asm("mov.b64 %0, {%1, %2};" : "=l"(r) : "f"(lo), "f"(hi));
    return r;
}
__device__ __forceinline__ float2 unpack2(unsigned long long v) {
    float2 r;
    asm("mov.b64 {%0, %1}, %2;" : "=f"(r.x), "=f"(r.y) : "l"(v));
    return r;
}
// split float -> bf16x2 word pair helpers
__device__ __forceinline__ uint32_t bf2w(float a, float b) {
    __nv_bfloat162 p = __floats2bfloat162_rn(a, b);
    return *reinterpret_cast<uint32_t*>(&p);
}

// ---------------- warp MMA helpers (base-ISA) ----------------
__device__ __forceinline__ uint32_t smem_u32(const void* p) {
    uint32_t a;
    asm("{ .reg .u64 t; cvta.to.shared.u64 t, %1; cvt.u32.u64 %0, t; }"
        : "=r"(a) : "l"(p));
    return a;
}
__device__ __forceinline__ void mma16816(float* c, const uint32_t* a, const uint32_t* b) {
    asm volatile(
        "mma.sync.aligned.m16n8k16.row.col.f32.bf16.bf16.f32 "
        "{%0,%1,%2,%3}, {%4,%5,%6,%7}, {%8,%9}, {%0,%1,%2,%3};"
        : "+f"(c[0]), "+f"(c[1]), "+f"(c[2]), "+f"(c[3])
        : "r"(a[0]), "r"(a[1]), "r"(a[2]), "r"(a[3]), "r"(b[0]), "r"(b[1]));
}
__device__ __forceinline__ void ldsm_x4(uint32_t* r, uint32_t addr) {
    asm volatile("ldmatrix.sync.aligned.m8n8.x4.shared.b16 {%0,%1,%2,%3}, [%4];"
                 : "=r"(r[0]), "=r"(r[1]), "=r"(r[2]), "=r"(r[3]) : "r"(addr));
}
__device__ __forceinline__ void ldsm_x2(uint32_t* r, uint32_t addr) {
    asm volatile("ldmatrix.sync.aligned.m8n8.x2.shared.b16 {%0,%1}, [%2];"
                 : "=r"(r[0]), "=r"(r[1]) : "r"(addr));
}

// ---------------- weight pre-transpose + bf16 hi/lo split -----------------
template<int K, int N>
__device__ __forceinline__ void wsplit_body(const float* __restrict__ W,
                                            __nv_bfloat16* __restrict__ Th,
                                            __nv_bfloat16* __restrict__ Tl) {
    int total = K * N;
    for (int idx = blockIdx.x * blockDim.x + threadIdx.x; idx < total;
         idx += gridDim.x * blockDim.x) {
        int n = idx / K, k = idx - n * K;
        float x = __ldg(&W[(size_t)k * N + n]);
        __nv_bfloat16 h = __float2bfloat16(x);
        float r = x - __bfloat162float(h);
        Th[idx] = h;
        Tl[idx] = __float2bfloat16(r);
    }
}
__global__ void wsplit_fc_kernel(const float* __restrict__ W) {
    wsplit_body<3136, 512>(W, g_WfcT_h, g_WfcT_l);
}
__global__ void wsplit_c2_kernel(const float* __restrict__ W) {
    wsplit_body<512, 64>(W, g_W2T_h, g_W2T_l);
}
__global__ void wsplit_c3_kernel(const float* __restrict__ W) {
    wsplit_body<576, 64>(W, g_W3T_h, g_W3T_l);
}

// ============ HMMA bf16x3 GEMM: C = relu(A*B^T + bias) ============
// A given as bf16 hi/lo pair [m][k] (im2col-gatherable); B^T bf16 hi/lo [N][K].
// CTA: 128(M) x 64(N); 8 warps 4x2; warptile 32x32; m16n8k16; 3 split terms.
// A-staging is pure 16B vector copy (im2col segments are CI-contiguous).
// OUTBF=1: epilogue writes bf16 hi/lo pair; OUTBF=0: fp32.
template<int NTOT, int K, int IM2COL, int P, int PW, int S, int IW, int CI,
         int KW, int OUTBF>
__device__ void mgemm_body(const __nv_bfloat16* __restrict__ Ah,
                           const __nv_bfloat16* __restrict__ Al,
                           const __nv_bfloat16* __restrict__ BhT,
                           const __nv_bfloat16* __restrict__ BlT,
                           const float* __restrict__ bias,
                           __nv_bfloat16* __restrict__ outh,
                           __nv_bfloat16* __restrict__ outl,
                           float* __restrict__ outf)
{
    extern __shared__ char smem[];
    constexpr int LDA = 72;                       // bf16 per smem row
    constexpr int A_BYTES = 128 * LDA * 2;        // 18432
    constexpr int B_BYTES = 64 * LDA * 2;         // 9216
    constexpr int OFF_AH  = 0;
    constexpr int OFF_AL  = A_BYTES;
    constexpr int OFF_BH  = 2 * A_BYTES;
    constexpr int OFF_BL  = 2 * A_BYTES + B_BYTES;
    constexpr int OFF_KO  = 2 * A_BYTES + 2 * B_BYTES;
    constexpr int OFF_ROW = OFF_KO + (IM2COL ? K * 4 : 0);

    const int t = threadIdx.x;
    const int wid = t >> 5, L = t & 31;
    const int wm = wid >> 1, wn = wid & 1;
    const int g = L >> 2, tc = L & 3;
    const int bm = blockIdx.y * 128;
    const int bn = blockIdx.x * 64;
    uint32_t sbase = smem_u32(smem);
    int* s_koff = (int*)(smem + OFF_KO);
    int* s_row  = (int*)(smem + OFF_ROW);

    if (IM2COL) {
        for (int i = t; i < K; i += 256) {
            int ky = i / (KW * CI);
            int r  = i - ky * (KW * CI);
            int kx = r / CI;
            int ci = r - kx * CI;
            s_koff[i] = (ky * IW + kx) * CI + ci;
        }
        if (t < 128) {
            int m = bm + t;
            int n = m / P;
            int p = m - n * P;
            int py = p / PW;
            int px = p - py * PW;
            s_row[t] = n * (IW * IW * CI) + (py * S * IW + px * S) * CI;
        }
        __syncthreads();
    }

    // per-lane ldmatrix base addresses (bytes)
    const uint32_t aoffL = (uint32_t)((wm * 32 + (L & 15)) * (LDA * 2) + (L >> 4) * 16);
    const uint32_t boffL = (uint32_t)((wn * 32 + (L & 7)) * (LDA * 2) + ((L >> 3) & 1) * 16);
    const uint32_t aH = sbase + OFF_AH + aoffL;
    const uint32_t aL = sbase + OFF_AL + aoffL;
    const uint32_t bH = sbase + OFF_BH + boffL;
    const uint32_t bL = sbase + OFF_BL + boffL;

    float acc[2][4][4];
#pragma unroll
    for (int i = 0; i < 2; i++)
#pragma unroll
        for (int j = 0; j < 4; j++)
#pragma unroll
            for (int q = 0; q < 4; q++) acc[i][j][q] = 0.f;

    // A-stage copy geometry: per chunk each row needs 128 bytes (64 bf16).
    // conv2 (CI=32): 2 contiguous 64B segments; conv3 (CI=64)/fc: 1 x 128B.
    constexpr int UPS = (IM2COL && CI == 32) ? 4 : 8;   // 16B units per segment

    constexpr int NCH = K / 64;
    for (int ch = 0; ch < NCH; ch++) {
        const int k0 = ch * 64;
        // ---- stage A: vector copy bf16 hi/lo (1024 x 16B units per split) ----
        for (int u = t; u < 1024; u += 256) {
            int r = u >> 3;          // row
            int i = u & 7;           // 16B unit within row
            int seg = i / UPS;
            int isg = i - seg * UPS;
            size_t src;
            if (IM2COL) src = (size_t)s_row[r] + s_koff[k0 + seg * CI] + isg * 8;
            else        src = (size_t)(bm + r) * K + k0 + i * 8;
            uint4 vh = *(const uint4*)(Ah + src);
            uint4 vl = *(const uint4*)(Al + src);
            *(uint4*)(smem + OFF_AH + r * (LDA * 2) + i * 16) = vh;
            *(uint4*)(smem + OFF_AL + r * (LDA * 2) + i * 16) = vl;
        }
        // ---- stage B: 64x64 bf16 hi/lo as 32-bit words ----
        for (int e = t; e < 64 * 32; e += 256) {
            int n = e >> 5, wq = e & 31;
            size_t srcw = ((size_t)(bn + n) * K + k0) / 2 + wq;
            uint32_t vh = ((const uint32_t*)BhT)[srcw];
            uint32_t vl = ((const uint32_t*)BlT)[srcw];
            ((uint32_t*)(smem + OFF_BH))[n * (LDA / 2) + wq] = vh;
            ((uint32_t*)(smem + OFF_BL))[n * (LDA / 2) + wq] = vl;
        }
        __syncthreads();

#pragma unroll
        for (int ks = 0; ks < 4; ks++) {
            uint32_t ah[2][4], al[2][4], bh[4][2], bl[4][2];
#pragma unroll
            for (int mt = 0; mt < 2; mt++) {
                ldsm_x4(ah[mt], aH + mt * 16 * (LDA * 2) + ks * 32);
                ldsm_x4(al[mt], aL + mt * 16 * (LDA * 2) + ks * 32);
            }
#pragma unroll
            for (int nt = 0; nt < 4; nt++) {
                ldsm_x2(bh[nt], bH + nt * 8 * (LDA * 2) + ks * 32);
                ldsm_x2(bl[nt], bL + nt * 8 * (LDA * 2) + ks * 32);
            }
#pragma unroll
            for (int mt = 0; mt < 2; mt++)
#pragma unroll
                for (int nt = 0; nt < 4; nt++) {
                    mma16816(acc[mt][nt], ah[mt], bh[nt]);
                    mma16816(acc[mt][nt], ah[mt], bl[nt]);
                    mma16816(acc[mt][nt], al[mt], bh[nt]);
                }
        }
        __syncthreads();
    }

    // ---- epilogue: c-frag layout, bias + relu; bf16-split or fp32 out ----
#pragma unroll
    for (int mt = 0; mt < 2; mt++) {
#pragma unroll
        for (int nt = 0; nt < 4; nt++) {
            int col = bn + wn * 32 + nt * 8 + tc * 2;
            float b0 = __ldg(&bias[col]);
            float b1 = __ldg(&bias[col + 1]);
            int r0 = bm + wm * 32 + mt * 16 + g;
            float v00 = fmaxf(acc[mt][nt][0] + b0, 0.f);
            float v01 = fmaxf(acc[mt][nt][1] + b1, 0.f);
            float v10 = fmaxf(acc[mt][nt][2] + b0, 0.f);
            float v11 = fmaxf(acc[mt][nt][3] + b1, 0.f);
            if (OUTBF) {
                // hi = bf16(v); lo = bf16(v - hi)
                float h00 = __bfloat162float(__float2bfloat16(v00));
                float h01 = __bfloat162float(__float2bfloat16(v01));
                float h10 = __bfloat162float(__float2bfloat16(v10));
                float h11 = __bfloat162float(__float2bfloat16(v11));
                *(uint32_t*)&outh[(size_t)r0 * NTOT + col]       = bf2w(v00, v01);
                *(uint32_t*)&outl[(size_t)r0 * NTOT + col]       = bf2w(v00 - h00, v01 - h01);
                *(uint32_t*)&outh[(size_t)(r0 + 8) * NTOT + col] = bf2w(v10, v11);
                *(uint32_t*)&outl[(size_t)(r0 + 8) * NTOT + col] = bf2w(v10 - h10, v11 - h11);
            } else {
                float2 v0 = {v00, v01}, v1 = {v10, v11};
                *(float2*)&outf[(size_t)r0 * NTOT + col]       = v0;
                *(float2*)&outf[(size_t)(r0 + 8) * NTOT + col] = v1;
            }
        }
    }
}

// conv2: A = im2col(c1 bf16 pair), M=165888, K=512, N=64 -> bf16 pair
__global__ void __launch_bounds__(256) conv2m_kernel(const float* __restrict__ bias) {
    mgemm_body<64, 512, 1, 81, 9, 2, 20, 32, 4, 1>(
        g_c1h, g_c1l, g_W2T_h, g_W2T_l, bias, g_c2h, g_c2l, nullptr);
}
// conv3: A = im2col(c2 bf16 pair), M=100352, K=576, N=64 -> bf16 pair
__global__ void __launch_bounds__(256) conv3m_kernel(const float* __restrict__ bias) {
    mgemm_body<64, 576, 1, 49, 7, 1, 9, 64, 3, 1>(
        g_c2h, g_c2l, g_W3T_h, g_W3T_l, bias, g_c3h, g_c3l, nullptr);
}
// fc: A = c3 bf16 pair, M=2048, K=3136, N=512 -> fp32
__global__ void __launch_bounds__(256) fcm_kernel(const float* __restrict__ bias) {
    mgemm_body<512, 3136, 0, 1, 1, 1, 1, 1, 1, 0>(
        g_c3h, g_c3l, g_WfcT_h, g_WfcT_l, bias, nullptr, nullptr, g_feat);
}

// ================= scalar implicit-GEMM conv1 (f32x2), bf16-pair output ====
template<int P, int PW, int S, int IW, int CI, int OC, int K, int KW, int BM>
__device__ __forceinline__ void convgemm_body(
    const float* __restrict__ in, const float* __restrict__ Wt,
    const float* __restrict__ bias,
    __nv_bfloat16* __restrict__ outh, __nv_bfloat16* __restrict__ outl)
{
    constexpr int IMGSZ = IW * IW * CI;
    constexpr int AS  = (BM == 128) ? 136 : 260;
    constexpr int BSS = OC + 4;
    constexpr int TN  = OC / 4;
    constexpr int LA  = BM / 16;
    constexpr int NIT = K / 16;

    __shared__ int s_koff[K];
    __shared__ __align__(16) float As[16][AS];
    __shared__ __align__(16) float Bs[16][BSS];

    const int t  = threadIdx.x;
    const int m0 = blockIdx.x * BM;

    for (int i = t; i < K; i += 256) {
        int ky = i / (KW * CI);
        int r  = i - ky * (KW * CI);
        int kx = r / CI;
        int ci = r - kx * CI;
        s_koff[i] = (ky * IW + kx) * CI + ci;
    }
    int rowoff[LA];
#pragma unroll
    for (int l = 0; l < LA; l++) {
        int m  = m0 + (t >> 4) + 16 * l;
        int n  = m / P;
        int p  = m - n * P;
        int py = p / PW;
        int px = p - py * PW;
        rowoff[l] = n * IMGSZ + (py * S * IW + px * S) * CI;
    }
    __syncthreads();

    const int tm  = t / TN;
    const int tn  = t - tm * TN;
    const int kkA = t & 15;
    const int mrA = t >> 4;
    const int brn = (OC == 64) ? (t >> 4) : (t >> 3);
    const int bcn = (OC == 64) ? ((t & 15) * 4) : ((t & 7) * 4);
    const bool bact = (OC == 64) || (t < 128);

    float  aReg[LA];
    float4 bReg;
    auto load_tile = [&](int k0) {
        int kof = s_koff[k0 + kkA];
#pragma unroll
        for (int l = 0; l < LA; l++)
            aReg[l] = __ldg(&in[(size_t)rowoff[l] + kof]);
        if (bact)
            bReg = *(const float4*)&Wt[(size_t)(k0 + brn) * OC + bcn];
    };
    auto store_tile = [&]() {
#pragma unroll
        for (int l = 0; l < LA; l++)
            As[kkA][mrA + 16 * l] = aReg[l];
        if (bact)
            *(float4*)&Bs[brn][bcn] = bReg;
    };

    unsigned long long acc2[4][4];
#pragma unroll
    for (int i = 0; i < 4; i++)
#pragma unroll
        for (int j = 0; j < 4; j++) acc2[i][j] = 0ull;

    load_tile(0);
    store_tile();
    __syncthreads();

    for (int it = 1; it <= NIT; it++) {
        if (it < NIT) load_tile(it * 16);
#pragma unroll
        for (int kk = 0; kk < 16; kk++) {
            const unsigned long long* ap =
                reinterpret_cast<const unsigned long long*>(&As[kk][tm * 8]);
            unsigned long long a2[4] = {ap[0], ap[1], ap[2], ap[3]};
            float4 bq = *(const float4*)&Bs[kk][tn * 4];
            unsigned long long b2[4] = {pack2(bq.x, bq.x), pack2(bq.y, bq.y),
                                        pack2(bq.z, bq.z), pack2(bq.w, bq.w)};
#pragma unroll
            for (int i = 0; i < 4; i++)
#pragma unroll
                for (int j = 0; j < 4; j++)
                    fma2(acc2[i][j], a2[i], b2[j]);
        }
        if (it < NIT) {
            __syncthreads();
            store_tile();
            __syncthreads();
        }
    }

    float4 bv = *(const float4*)&bias[tn * 4];
    float bb[4] = {bv.x, bv.y, bv.z, bv.w};
#pragma unroll
    for (int i2 = 0; i2 < 4; i2++) {
        int mlo = m0 + tm * 8 + 2 * i2;
        float2 u0 = unpack2(acc2[i2][0]);
        float2 u1 = unpack2(acc2[i2][1]);
        float2 u2 = unpack2(acc2[i2][2]);
        float2 u3 = unpack2(acc2[i2][3]);
        float vlo[4] = {fmaxf(u0.x + bb[0], 0.f), fmaxf(u1.x + bb[1], 0.f),
                        fmaxf(u2.x + bb[2], 0.f), fmaxf(u3.x + bb[3], 0.f)};
        float vhi[4] = {fmaxf(u0.y + bb[0], 0.f), fmaxf(u1.y + bb[1], 0.f),
                        fmaxf(u2.y + bb[2], 0.f), fmaxf(u3.y + bb[3], 0.f)};
#pragma unroll
        for (int half = 0; half < 2; half++) {
            const float* v = half ? vhi : vlo;
            size_t base = (size_t)(mlo + half) * OC + tn * 4;
            float h0 = __bfloat162float(__float2bfloat16(v[0]));
            float h1 = __bfloat162float(__float2bfloat16(v[1]));
            float h2 = __bfloat162float(__float2bfloat16(v[2]));
            float h3 = __bfloat162float(__float2bfloat16(v[3]));
            uint2 wh = {bf2w(v[0], v[1]), bf2w(v[2], v[3])};
            uint2 wl = {bf2w(v[0] - h0, v[1] - h1), bf2w(v[2] - h2, v[3] - h3)};
            *(uint2*)&outh[base] = wh;
            *(uint2*)&outl[base] = wl;
        }
    }
}

__global__ void __launch_bounds__(256) conv1g_kernel(
    const float* __restrict__ img, const float* __restrict__ W,
    const float* __restrict__ bias)
{
    convgemm_body<400, 20, 4, 84, 3, 32, 192, 8, 256>(img, W, bias, g_c1h, g_c1l);
}

// ---------------- xw: SGEMM 64x64x16 f32x2 (EPI: biases + one-hot) --------
__device__ __forceinline__ void xw_body(
    const float* __restrict__ A, const float* __restrict__ B,
    float* __restrict__ C, int N, int K, int ldb,
    const float* __restrict__ bias1, const float* __restrict__ bias2,
    const float* __restrict__ WihFull, const int* __restrict__ pos)
{
    __shared__ __align__(16) float As[16][68];
    __shared__ __align__(16) float Bs[16][68];
    int bm = blockIdx.y * 64, bn = blockIdx.x * 64;
    int t = threadIdx.x;
    int tm = t >> 4, tn = t & 15;

    unsigned long long acc2[2][4];
#pragma unroll
    for (int i = 0; i < 2; i++)
#pragma unroll
        for (int j = 0; j < 4; j++) acc2[i][j] = 0ull;

    int ar = t >> 2, ac = (t & 3) * 4;

    float4 avR, bvR;
    auto load_tile = [&](int k0) {
        avR = *(const float4*)(A + (size_t)(bm + ar) * K + k0 + ac);
        bvR = *(const float4*)(B + (size_t)(bn + ar) * ldb + k0 + ac);
    };
    auto store_tile = [&]() {
        As[ac + 0][ar] = avR.x; As[ac + 1][ar] = avR.y;
        As[ac + 2][ar] = avR.z; As[ac + 3][ar] = avR.w;
        Bs[ac + 0][ar] = bvR.x; Bs[ac + 1][ar] = bvR.y;
        Bs[ac + 2][ar] = bvR.z; Bs[ac + 3][ar] = bvR.w;
    };

    const int NIT = K / 16;
    load_tile(0);
    store_tile();
    __syncthreads();

    for (int it = 1; it <= NIT; it++) {
        if (it < NIT) load_tile(it * 16);
#pragma unroll
        for (int kk = 0; kk < 16; kk++) {
            const unsigned long long* ap =
                reinterpret_cast<const unsigned long long*>(&As[kk][tm * 4]);
            unsigned long long a2[2] = {ap[0], ap[1]};
            float4 bq = *(const float4*)&Bs[kk][tn * 4];
            unsigned long long b2[4] = {pack2(bq.x, bq.x), pack2(bq.y, bq.y),
                                        pack2(bq.z, bq.z), pack2(bq.w, bq.w)};
#pragma unroll
            for (int i = 0; i < 2; i++)
#pragma unroll
                for (int j = 0; j < 4; j++)
                    fma2(acc2[i][j], a2[i], b2[j]);
        }
        if (it < NIT) {
            __syncthreads();
            store_tile();
            __syncthreads();
        }
    }
#pragma unroll
    for (int i2 = 0; i2 < 2; i2++) {
        float2 u[4];
#pragma unroll
        for (int j = 0; j < 4; j++) u[j] = unpack2(acc2[i2][j]);
#pragma unroll
        for (int half = 0; half < 2; half++) {
            int row = bm + tm * 4 + 2 * i2 + half;
            int p0 = pos[2 * row], p1 = pos[2 * row + 1];
#pragma unroll
            for (int j = 0; j < 4; j++) {
                int col = bn + tn * 4 + j;
                float v = half ? u[j].y : u[j].x;
                v += bias1[col] + bias2[col]
                   + WihFull[(size_t)col * 532 + 512 + p0]
                   + WihFull[(size_t)col * 532 + 522 + p1];
                C[(size_t)row * N + col] = v;
            }
        }
    }
}

__global__ void __launch_bounds__(256) xw_kernel(
    const float* __restrict__ Wih, const float* __restrict__ bih,
    const float* __restrict__ bhh, const int* __restrict__ pos)
{
    xw_body(g_feat, Wih, g_xw, 512, 512, 532, bih, bhh, Wih, pos);
}

// ---------------- persistent LSTM: 32 blocks x 128 threads --------------
__device__ __forceinline__ float sigmoidf_(float x) {
    return 1.0f / (1.0f + __expf(-x));
}

__global__ void __launch_bounds__(128) lstm_kernel(
    const int* __restrict__ done, const float* __restrict__ h0,
    const float* __restrict__ c0, const float* __restrict__ Whh,
    float* __restrict__ out)
{
    int k = blockIdx.x;
    int t = threadIdx.x;
    int lane = t & 31, w = t >> 5;

    __shared__ float whh_s[16][HID];
    __shared__ float h_sh[HID][BBATCH];
    __shared__ float c_s[4][BBATCH];
    __shared__ float gate_s[4][4][BBATCH];
    __shared__ float m_s[BBATCH];

    for (int idx = t; idx < 16 * HID; idx += 128) {
        int r = idx >> 7, j = idx & 127;
        int G = (r >> 2) * HID + k * 4 + (r & 3);
        whh_s[r][j] = Whh[(size_t)G * HID + j];
    }
    c_s[w][lane] = c0[lane * HID + k * 4 + w];
    __stcg(&g_hT[0][(k * 4 + w) * BBATCH + lane], h0[lane * HID + k * 4 + w]);
    __threadfence();
    __syncthreads();
    unsigned target = 32;
    if (t == 0) {
        atomicAdd(&g_bar, 1u);
        while (*((volatile unsigned*)&g_bar) < target) {}
    }
    __syncthreads();

    float h_last = 0.f;
    for (int step = 0; step < TSTEPS; step++) {
        int p = step & 1;
        if (t < 32) m_s[t] = 1.0f - (float)done[step * BBATCH + t];
        __syncthreads();
        for (int idx = t; idx < HID * BBATCH; idx += 128) {
            h_sh[idx >> 5][idx & 31] = __ldcg(&g_hT[p][idx]) * m_s[idx & 31];
        }
        __syncthreads();

        float acc[4];
        const float* xwr = g_xw + (size_t)(step * BBATCH + lane) * 512 + w * HID + k * 4;
#pragma unroll
        for (int ul = 0; ul < 4; ul++) acc[ul] = xwr[ul];
#pragma unroll 4
        for (int j = 0; j < HID; j++) {
            float hv = h_sh[j][lane];
#pragma unroll
            for (int ul = 0; ul < 4; ul++) acc[ul] += hv * whh_s[w * 4 + ul][j];
        }
#pragma unroll
        for (int ul = 0; ul < 4; ul++) gate_s[w][ul][lane] = acc[ul];
        __syncthreads();

        float iv = sigmoidf_(gate_s[0][w][lane]);
        float fv = sigmoidf_(gate_s[1][w][lane]);
        float gv = tanhf(gate_s[2][w][lane]);
        float ov = sigmoidf_(gate_s[3][w][lane]);
        float cc = fv * (c_s[w][lane] * m_s[lane]) + iv * gv;
        c_s[w][lane] = cc;
        float hh = ov * tanhf(cc);
        h_last = hh;
        __stcg(&g_hT[1 - p][(k * 4 + w) * BBATCH + lane], hh);
        g_hs[(size_t)(step * BBATCH + lane) * HID + k * 4 + w] = hh;
        __threadfence();
        __syncthreads();
        target += 32;
        if (t == 0) {
            atomicAdd(&g_bar, 1u);
            while (*((volatile unsigned*)&g_bar) < target) {}
        }
        __syncthreads();
    }
    out[12288 + lane * HID + k * 4 + w] = h_last;
    out[16384 + lane * HID + k * 4 + w] = c_s[w][lane];
}

// ---------------- heads: logits (2048x5) + value (2048x1) ---------------
__global__ void heads_kernel(
    const float* __restrict__ Wp, const float* __restrict__ bp,
    const float* __restrict__ Wv, const float* __restrict__ bv,
    float* __restrict__ out)
{
    int row = blockIdx.x * 8 + threadIdx.y;
    int lane = threadIdx.x;
    const float* h = g_hs + (size_t)row * HID;
    float4 hv = *(const float4*)&h[lane * 4];
    float vals[4] = {hv.x, hv.y, hv.z, hv.w};
    float r[6];
#pragma unroll
    for (int a = 0; a < 5; a++) {
        float s = 0.f;
#pragma unroll
        for (int q = 0; q < 4; q++) s += vals[q] * __ldg(&Wp[(lane * 4 + q) * 5 + a]);
        r[a] = s;
    }
    {
        float s = 0.f;
#pragma unroll
        for (int q = 0; q < 4; q++) s += vals[q] * __ldg(&Wv[lane * 4 + q]);
        r[5] = s;
    }
#pragma unroll
    for (int a = 0; a < 6; a++)
#pragma unroll
        for (int off = 16; off > 0; off >>= 1)
            r[a] += __shfl_xor_sync(0xffffffffu, r[a], off);
    if (lane == 0) {
#pragma unroll
        for (int a = 0; a < 5; a++) out[(size_t)row * 5 + a] = r[a] + __ldg(&bp[a]);
        out[10240 + row] = r[5] + __ldg(&bv[0]);
    }
}

// ---------------- launch ----------------
extern "C" void kernel_launch(void* const* d_in, const int* in_sizes, int n_in,
                              void* d_out, int out_size)
{
    const float* image    = (const float*)d_in[0];
    const int*   position = (const int*)d_in[1];
    const int*   done     = (const int*)d_in[2];
    const float* h0       = (const float*)d_in[3];
    const float* c0       = (const float*)d_in[4];
    const float* W1  = (const float*)d_in[5];
    const float* b1  = (const float*)d_in[6];
    const float* W2  = (const float*)d_in[7];
    const float* b2  = (const float*)d_in[8];
    const float* W3  = (const float*)d_in[9];
    const float* b3  = (const float*)d_in[10];
    const float* Wfc = (const float*)d_in[11];
    const float* bfc = (const float*)d_in[12];
    const float* Wih = (const float*)d_in[13];
    const float* Whh = (const float*)d_in[14];
    const float* bih = (const float*)d_in[15];
    const float* bhh = (const float*)d_in[16];
    const float* Wp  = (const float*)d_in[17];
    const float* bp  = (const float*)d_in[18];
    const float* Wv  = (const float*)d_in[19];
    const float* bv  = (const float*)d_in[20];
    float* out = (float*)d_out;

    const int SM_C2 = 55296 + 512 * 4 + 512;
    const int SM_C3 = 55296 + 576 * 4 + 512;
    const int SM_FC = 55296;
    cudaFuncSetAttribute(conv2m_kernel, cudaFuncAttributeMaxDynamicSharedMemorySize, SM_C2);
    cudaFuncSetAttribute(conv3m_kernel, cudaFuncAttributeMaxDynamicSharedMemorySize, SM_C3);
    cudaFuncSetAttribute(fcm_kernel,   cudaFuncAttributeMaxDynamicSharedMemorySize, SM_FC);

    // ordered so launch #4 (ncu's profiled one) is conv2m
    init_kernel<<<1, 32>>>();
    conv1g_kernel<<<819200 / 256, 256>>>(image, W1, b1);
    wsplit_c2_kernel<<<32, 256>>>(W2);
    conv2m_kernel<<<dim3(1, 165888 / 128), 256, SM_C2>>>(b2);
    wsplit_c3_kernel<<<32, 256>>>(W3);
    conv3m_kernel<<<dim3(1, 100352 / 128), 256, SM_C3>>>(b3);
    wsplit_fc_kernel<<<512, 256>>>(Wfc);
    fcm_kernel<<<dim3(8, 2048 / 128), 256, SM_FC>>>(bfc);
    xw_kernel<<<dim3(8, 32), 256>>>(Wih, bih, bhh, position);
    lstm_kernel<<<32, 128>>>(done, h0, c0, Whh, out);
    heads_kernel<<<256, dim3(32, 8)>>>(Wp, bp, Wv, bv, out);
}

// round 14
// speedup vs baseline: 1.4977x; 1.1427x over previous
#include <cuda_runtime.h>
#include <cuda_bf16.h>
#include <cstdint>

// ---------------- problem constants ----------------
#define NIMG 2048          // T*B
#define TSTEPS 64
#define BBATCH 32
#define HID 128

// ---------------- device scratch -------------------
// activations stored as bf16 hi/lo split pairs [m][k]
__device__ __nv_bfloat16 g_c1h[NIMG * 400 * 32];
__device__ __nv_bfloat16 g_c1l[NIMG * 400 * 32];
__device__ __nv_bfloat16 g_c2h[NIMG * 81 * 64];
__device__ __nv_bfloat16 g_c2l[NIMG * 81 * 64];
__device__ __nv_bfloat16 g_c3h[NIMG * 3136];
__device__ __nv_bfloat16 g_c3l[NIMG * 3136];
__device__ float g_feat[NIMG * 512];       // fc out (fp32)
__device__ float g_xw[NIMG * 512];         // x@Wih^T + biases + one-hot
__device__ float g_hT[2][HID * BBATCH];
__device__ float g_hs[NIMG * HID];
__device__ unsigned g_bar;

// bf16 hi/lo split weights, transposed to [N][K]
__device__ __nv_bfloat16 g_WfcT_h[512 * 3136];
__device__ __nv_bfloat16 g_WfcT_l[512 * 3136];
__device__ __nv_bfloat16 g_W2T_h[64 * 512];
__device__ __nv_bfloat16 g_W2T_l[64 * 512];
__device__ __nv_bfloat16 g_W3T_h[64 * 576];
__device__ __nv_bfloat16 g_W3T_l[64 * 576];

__global__ void init_kernel() {
    if (threadIdx.x == 0) g_bar = 0u;
}

// ---------------- packed f32x2 helpers ----------------
__device__ __forceinline__ void fma2(unsigned long long& d,
                                     unsigned long long a,
                                     unsigned long long b) {
    asm("fma.rn.f32x2 %0, %1, %2, %3;" : "=l"(d) : "l"(a), "l"(b), "l"(d));
}
__device__ __forceinline__ unsigned long long pack2(float lo, float hi) {
    unsigned long long r;
    asm("mov.b64 %0, {%1, %2};" : "=l"(r) : "f"(lo), "f"(hi));
    return r;
}
__device__ __forceinline__ float2 unpack2(unsigned long long v) {
    float2 r;
    asm("mov.b64 {%0, %1}, %2;" : "=f"(r.x), "=f"(r.y) : "l"(v));
    return r;
}
__device__ __forceinline__ uint32_t bf2w(float a, float b) {
    __nv_bfloat162 p = __floats2bfloat162_rn(a, b);
    return *reinterpret_cast<uint32_t*>(&p);
}

// ---------------- warp MMA + async-copy helpers (base-ISA) -----------------
__device__ __forceinline__ uint32_t smem_u32(const void* p) {
    uint32_t a;
    asm("{ .reg .u64 t; cvta.to.shared.u64 t, %1; cvt.u32.u64 %0, t; }"
        : "=r"(a) : "l"(p));
    return a;
}
__device__ __forceinline__ void mma16816(float* c, const uint32_t* a, const uint32_t* b) {
    asm volatile(
        "mma.sync.aligned.m16n8k16.row.col.f32.bf16.bf16.f32 "
        "{%0,%1,%2,%3}, {%4,%5,%6,%7}, {%8,%9}, {%0,%1,%2,%3};"
        : "+f"(c[0]), "+f"(c[1]), "+f"(c[2]), "+f"(c[3])
        : "r"(a[0]), "r"(a[1]), "r"(a[2]), "r"(a[3]), "r"(b[0]), "r"(b[1]));
}
__device__ __forceinline__ void ldsm_x4(uint32_t* r, uint32_t addr) {
    asm volatile("ldmatrix.sync.aligned.m8n8.x4.shared.b16 {%0,%1,%2,%3}, [%4];"
                 : "=r"(r[0]), "=r"(r[1]), "=r"(r[2]), "=r"(r[3]) : "r"(addr));
}
__device__ __forceinline__ void ldsm_x2(uint32_t* r, uint32_t addr) {
    asm volatile("ldmatrix.sync.aligned.m8n8.x2.shared.b16 {%0,%1}, [%2];"
                 : "=r"(r[0]), "=r"(r[1]) : "r"(addr));
}
__device__ __forceinline__ void cpasync16(uint32_t dst, const void* src) {
    asm volatile("cp.async.cg.shared.global [%0], [%1], 16;"
                 :: "r"(dst), "l"(src) : "memory");
}
#define CP_COMMIT() asm volatile("cp.async.commit_group;" ::: "memory")
#define CP_WAIT1()  asm volatile("cp.async.wait_group 1;" ::: "memory")
#define CP_WAIT0()  asm volatile("cp.async.wait_group 0;" ::: "memory")

// ---------------- weight pre-transpose + bf16 hi/lo split -----------------
template<int K, int N>
__device__ __forceinline__ void wsplit_body(const float* __restrict__ W,
                                            __nv_bfloat16* __restrict__ Th,
                                            __nv_bfloat16* __restrict__ Tl) {
    int total = K * N;
    for (int idx = blockIdx.x * blockDim.x + threadIdx.x; idx < total;
         idx += gridDim.x * blockDim.x) {
        int n = idx / K, k = idx - n * K;
        float x = __ldg(&W[(size_t)k * N + n]);
        __nv_bfloat16 h = __float2bfloat16(x);
        float r = x - __bfloat162float(h);
        Th[idx] = h;
        Tl[idx] = __float2bfloat16(r);
    }
}
__global__ void wsplit_fc_kernel(const float* __restrict__ W) {
    wsplit_body<3136, 512>(W, g_WfcT_h, g_WfcT_l);
}
__global__ void wsplit_c2_kernel(const float* __restrict__ W) {
    wsplit_body<512, 64>(W, g_W2T_h, g_W2T_l);
}
__global__ void wsplit_c3_kernel(const float* __restrict__ W) {
    wsplit_body<576, 64>(W, g_W3T_h, g_W3T_l);
}

// ============ HMMA bf16x3 GEMM, cp.async double-buffered ============
// A bf16 hi/lo pair [m][k] (im2col-gatherable); B^T bf16 hi/lo [N][K].
// CTA: 128(M) x 64(N); 8 warps 4x2; warptile 32x32; m16n8k16; 3 split terms.
// Chunk ch+1 is cp.async'd into buffer (ch+1)&1 while MMA consumes buffer ch&1.
template<int NTOT, int K, int IM2COL, int P, int PW, int S, int IW, int CI,
         int KW, int OUTBF>
__device__ void mgemm_body(const __nv_bfloat16* __restrict__ Ah,
                           const __nv_bfloat16* __restrict__ Al,
                           const __nv_bfloat16* __restrict__ BhT,
                           const __nv_bfloat16* __restrict__ BlT,
                           const float* __restrict__ bias,
                           __nv_bfloat16* __restrict__ outh,
                           __nv_bfloat16* __restrict__ outl,
                           float* __restrict__ outf)
{
    extern __shared__ char smem[];
    constexpr int LDAB = 144;                     // bytes per smem row (72 bf16)
    constexpr int A_BYTES = 128 * LDAB;           // 18432
    constexpr int B_BYTES = 64 * LDAB;            // 9216
    constexpr int BUF_BYTES = 2 * A_BYTES + 2 * B_BYTES;   // 55296
    constexpr int OFF_AH  = 0;
    constexpr int OFF_AL  = A_BYTES;
    constexpr int OFF_BH  = 2 * A_BYTES;
    constexpr int OFF_BL  = 2 * A_BYTES + B_BYTES;
    constexpr int OFF_KO  = 2 * BUF_BYTES;
    constexpr int OFF_ROW = OFF_KO + (IM2COL ? K * 4 : 0);

    const int t = threadIdx.x;
    const int wid = t >> 5, L = t & 31;
    const int wm = wid >> 1, wn = wid & 1;
    const int g = L >> 2, tc = L & 3;
    const int bm = blockIdx.y * 128;
    const int bn = blockIdx.x * 64;
    uint32_t sbase = smem_u32(smem);
    int* s_koff = (int*)(smem + OFF_KO);
    int* s_row  = (int*)(smem + OFF_ROW);

    if (IM2COL) {
        for (int i = t; i < K; i += 256) {
            int ky = i / (KW * CI);
            int r  = i - ky * (KW * CI);
            int kx = r / CI;
            int ci = r - kx * CI;
            s_koff[i] = (ky * IW + kx) * CI + ci;
        }
        if (t < 128) {
            int m = bm + t;
            int n = m / P;
            int p = m - n * P;
            int py = p / PW;
            int px = p - py * PW;
            s_row[t] = n * (IW * IW * CI) + (py * S * IW + px * S) * CI;
        }
        __syncthreads();
    }

    // per-lane ldmatrix offsets (within a buffer)
    const uint32_t aoffL = (uint32_t)((wm * 32 + (L & 15)) * LDAB + (L >> 4) * 16);
    const uint32_t boffL = (uint32_t)((wn * 32 + (L & 7)) * LDAB + ((L >> 3) & 1) * 16);

    // im2col segment geometry (16B units per contiguous segment)
    constexpr int UPS = (IM2COL && CI == 32) ? 4 : 8;

    // async-stage one 64-K chunk into buffer `buf`
    auto stage = [&](int ch, int buf) {
        const int k0 = ch * 64;
        const uint32_t sb = sbase + buf * BUF_BYTES;
        for (int u = t; u < 1024; u += 256) {
            int r = u >> 3, i = u & 7;
            int seg = i / UPS, isg = i - seg * UPS;
            size_t src;
            if (IM2COL) src = (size_t)s_row[r] + s_koff[k0 + seg * CI] + isg * 8;
            else        src = (size_t)(bm + r) * K + k0 + i * 8;
            cpasync16(sb + OFF_AH + r * LDAB + i * 16, Ah + src);
            cpasync16(sb + OFF_AL + r * LDAB + i * 16, Al + src);
        }
        for (int e = t; e < 512; e += 256) {
            int n = e >> 3, i = e & 7;
            size_t src = (size_t)(bn + n) * K + k0 + i * 8;
            cpasync16(sb + OFF_BH + n * LDAB + i * 16, BhT + src);
            cpasync16(sb + OFF_BL + n * LDAB + i * 16, BlT + src);
        }
    };

    float acc[2][4][4];
#pragma unroll
    for (int i = 0; i < 2; i++)
#pragma unroll
        for (int j = 0; j < 4; j++)
#pragma unroll
            for (int q = 0; q < 4; q++) acc[i][j][q] = 0.f;

    constexpr int NCH = K / 64;
    stage(0, 0);
    CP_COMMIT();

    for (int ch = 0; ch < NCH; ch++) {
        if (ch + 1 < NCH) {
            stage(ch + 1, (ch + 1) & 1);
            CP_COMMIT();
            CP_WAIT1();       // chunk ch complete (newest group may be in flight)
        } else {
            CP_WAIT0();
        }
        __syncthreads();

        const uint32_t sb = sbase + (uint32_t)(ch & 1) * BUF_BYTES;
        const uint32_t aH = sb + OFF_AH + aoffL;
        const uint32_t aL = sb + OFF_AL + aoffL;
        const uint32_t bH = sb + OFF_BH + boffL;
        const uint32_t bL = sb + OFF_BL + boffL;

#pragma unroll
        for (int ks = 0; ks < 4; ks++) {
            uint32_t ah[2][4], al[2][4], bh[4][2], bl[4][2];
#pragma unroll
            for (int mt = 0; mt < 2; mt++) {
                ldsm_x4(ah[mt], aH + mt * 16 * LDAB + ks * 32);
                ldsm_x4(al[mt], aL + mt * 16 * LDAB + ks * 32);
            }
#pragma unroll
            for (int nt = 0; nt < 4; nt++) {
                ldsm_x2(bh[nt], bH + nt * 8 * LDAB + ks * 32);
                ldsm_x2(bl[nt], bL + nt * 8 * LDAB + ks * 32);
            }
#pragma unroll
            for (int mt = 0; mt < 2; mt++)
#pragma unroll
                for (int nt = 0; nt < 4; nt++) {
                    mma16816(acc[mt][nt], ah[mt], bh[nt]);
                    mma16816(acc[mt][nt], ah[mt], bl[nt]);
                    mma16816(acc[mt][nt], al[mt], bh[nt]);
                }
        }
        __syncthreads();
    }

    // ---- epilogue: c-frag layout, bias + relu; bf16-split or fp32 out ----
#pragma unroll
    for (int mt = 0; mt < 2; mt++) {
#pragma unroll
        for (int nt = 0; nt < 4; nt++) {
            int col = bn + wn * 32 + nt * 8 + tc * 2;
            float b0 = __ldg(&bias[col]);
            float b1 = __ldg(&bias[col + 1]);
            int r0 = bm + wm * 32 + mt * 16 + g;
            float v00 = fmaxf(acc[mt][nt][0] + b0, 0.f);
            float v01 = fmaxf(acc[mt][nt][1] + b1, 0.f);
            float v10 = fmaxf(acc[mt][nt][2] + b0, 0.f);
            float v11 = fmaxf(acc[mt][nt][3] + b1, 0.f);
            if (OUTBF) {
                float h00 = __bfloat162float(__float2bfloat16(v00));
                float h01 = __bfloat162float(__float2bfloat16(v01));
                float h10 = __bfloat162float(__float2bfloat16(v10));
                float h11 = __bfloat162float(__float2bfloat16(v11));
                *(uint32_t*)&outh[(size_t)r0 * NTOT + col]       = bf2w(v00, v01);
                *(uint32_t*)&outl[(size_t)r0 * NTOT + col]       = bf2w(v00 - h00, v01 - h01);
                *(uint32_t*)&outh[(size_t)(r0 + 8) * NTOT + col] = bf2w(v10, v11);
                *(uint32_t*)&outl[(size_t)(r0 + 8) * NTOT + col] = bf2w(v10 - h10, v11 - h11);
            } else {
                float2 v0 = {v00, v01}, v1 = {v10, v11};
                *(float2*)&outf[(size_t)r0 * NTOT + col]       = v0;
                *(float2*)&outf[(size_t)(r0 + 8) * NTOT + col] = v1;
            }
        }
    }
}

// conv2: A = im2col(c1 bf16 pair), M=165888, K=512, N=64 -> bf16 pair
__global__ void __launch_bounds__(256) conv2m_kernel(const float* __restrict__ bias) {
    mgemm_body<64, 512, 1, 81, 9, 2, 20, 32, 4, 1>(
        g_c1h, g_c1l, g_W2T_h, g_W2T_l, bias, g_c2h, g_c2l, nullptr);
}
// conv3: A = im2col(c2 bf16 pair), M=100352, K=576, N=64 -> bf16 pair
__global__ void __launch_bounds__(256) conv3m_kernel(const float* __restrict__ bias) {
    mgemm_body<64, 576, 1, 49, 7, 1, 9, 64, 3, 1>(
        g_c2h, g_c2l, g_W3T_h, g_W3T_l, bias, g_c3h, g_c3l, nullptr);
}
// fc: A = c3 bf16 pair, M=2048, K=3136, N=512 -> fp32
__global__ void __launch_bounds__(256) fcm_kernel(const float* __restrict__ bias) {
    mgemm_body<512, 3136, 0, 1, 1, 1, 1, 1, 1, 0>(
        g_c3h, g_c3l, g_WfcT_h, g_WfcT_l, bias, nullptr, nullptr, g_feat);
}

// ================= scalar implicit-GEMM conv1 (f32x2), bf16-pair output ====
template<int P, int PW, int S, int IW, int CI, int OC, int K, int KW, int BM>
__device__ __forceinline__ void convgemm_body(
    const float* __restrict__ in, const float* __restrict__ Wt,
    const float* __restrict__ bias,
    __nv_bfloat16* __restrict__ outh, __nv_bfloat16* __restrict__ outl)
{
    constexpr int IMGSZ = IW * IW * CI;
    constexpr int AS  = (BM == 128) ? 136 : 260;
    constexpr int BSS = OC + 4;
    constexpr int TN  = OC / 4;
    constexpr int LA  = BM / 16;
    constexpr int NIT = K / 16;

    __shared__ int s_koff[K];
    __shared__ __align__(16) float As[16][AS];
    __shared__ __align__(16) float Bs[16][BSS];

    const int t  = threadIdx.x;
    const int m0 = blockIdx.x * BM;

    for (int i = t; i < K; i += 256) {
        int ky = i / (KW * CI);
        int r  = i - ky * (KW * CI);
        int kx = r / CI;
        int ci = r - kx * CI;
        s_koff[i] = (ky * IW + kx) * CI + ci;
    }
    int rowoff[LA];
#pragma unroll
    for (int l = 0; l < LA; l++) {
        int m  = m0 + (t >> 4) + 16 * l;
        int n  = m / P;
        int p  = m - n * P;
        int py = p / PW;
        int px = p - py * PW;
        rowoff[l] = n * IMGSZ + (py * S * IW + px * S) * CI;
    }
    __syncthreads();

    const int tm  = t / TN;
    const int tn  = t - tm * TN;
    const int kkA = t & 15;
    const int mrA = t >> 4;
    const int brn = (OC == 64) ? (t >> 4) : (t >> 3);
    const int bcn = (OC == 64) ? ((t & 15) * 4) : ((t & 7) * 4);
    const bool bact = (OC == 64) || (t < 128);

    float  aReg[LA];
    float4 bReg;
    auto load_tile = [&](int k0) {
        int kof = s_koff[k0 + kkA];
#pragma unroll
        for (int l = 0; l < LA; l++)
            aReg[l] = __ldg(&in[(size_t)rowoff[l] + kof]);
        if (bact)
            bReg = *(const float4*)&Wt[(size_t)(k0 + brn) * OC + bcn];
    };
    auto store_tile = [&]() {
#pragma unroll
        for (int l = 0; l < LA; l++)
            As[kkA][mrA + 16 * l] = aReg[l];
        if (bact)
            *(float4*)&Bs[brn][bcn] = bReg;
    };

    unsigned long long acc2[4][4];
#pragma unroll
    for (int i = 0; i < 4; i++)
#pragma unroll
        for (int j = 0; j < 4; j++) acc2[i][j] = 0ull;

    load_tile(0);
    store_tile();
    __syncthreads();

    for (int it = 1; it <= NIT; it++) {
        if (it < NIT) load_tile(it * 16);
#pragma unroll
        for (int kk = 0; kk < 16; kk++) {
            const unsigned long long* ap =
                reinterpret_cast<const unsigned long long*>(&As[kk][tm * 8]);
            unsigned long long a2[4] = {ap[0], ap[1], ap[2], ap[3]};
            float4 bq = *(const float4*)&Bs[kk][tn * 4];
            unsigned long long b2[4] = {pack2(bq.x, bq.x), pack2(bq.y, bq.y),
                                        pack2(bq.z, bq.z), pack2(bq.w, bq.w)};
#pragma unroll
            for (int i = 0; i < 4; i++)
#pragma unroll
                for (int j = 0; j < 4; j++)
                    fma2(acc2[i][j], a2[i], b2[j]);
        }
        if (it < NIT) {
            __syncthreads();
            store_tile();
            __syncthreads();
        }
    }

    float4 bv = *(const float4*)&bias[tn * 4];
    float bb[4] = {bv.x, bv.y, bv.z, bv.w};
#pragma unroll
    for (int i2 = 0; i2 < 4; i2++) {
        int mlo = m0 + tm * 8 + 2 * i2;
        float2 u0 = unpack2(acc2[i2][0]);
        float2 u1 = unpack2(acc2[i2][1]);
        float2 u2 = unpack2(acc2[i2][2]);
        float2 u3 = unpack2(acc2[i2][3]);
        float vlo[4] = {fmaxf(u0.x + bb[0], 0.f), fmaxf(u1.x + bb[1], 0.f),
                        fmaxf(u2.x + bb[2], 0.f), fmaxf(u3.x + bb[3], 0.f)};
        float vhi[4] = {fmaxf(u0.y + bb[0], 0.f), fmaxf(u1.y + bb[1], 0.f),
                        fmaxf(u2.y + bb[2], 0.f), fmaxf(u3.y + bb[3], 0.f)};
#pragma unroll
        for (int half = 0; half < 2; half++) {
            const float* v = half ? vhi : vlo;
            size_t base = (size_t)(mlo + half) * OC + tn * 4;
            float h0 = __bfloat162float(__float2bfloat16(v[0]));
            float h1 = __bfloat162float(__float2bfloat16(v[1]));
            float h2 = __bfloat162float(__float2bfloat16(v[2]));
            float h3 = __bfloat162float(__float2bfloat16(v[3]));
            uint2 wh = {bf2w(v[0], v[1]), bf2w(v[2], v[3])};
            uint2 wl = {bf2w(v[0] - h0, v[1] - h1), bf2w(v[2] - h2, v[3] - h3)};
            *(uint2*)&outh[base] = wh;
            *(uint2*)&outl[base] = wl;
        }
    }
}

__global__ void __launch_bounds__(256) conv1g_kernel(
    const float* __restrict__ img, const float* __restrict__ W,
    const float* __restrict__ bias)
{
    convgemm_body<400, 20, 4, 84, 3, 32, 192, 8, 256>(img, W, bias, g_c1h, g_c1l);
}

// ---------------- xw: SGEMM 64x64x16 f32x2 (EPI: biases + one-hot) --------
__device__ __forceinline__ void xw_body(
    const float* __restrict__ A, const float* __restrict__ B,
    float* __restrict__ C, int N, int K, int ldb,
    const float* __restrict__ bias1, const float* __restrict__ bias2,
    const float* __restrict__ WihFull, const int* __restrict__ pos)
{
    __shared__ __align__(16) float As[16][68];
    __shared__ __align__(16) float Bs[16][68];
    int bm = blockIdx.y * 64, bn = blockIdx.x * 64;
    int t = threadIdx.x;
    int tm = t >> 4, tn = t & 15;

    unsigned long long acc2[2][4];
#pragma unroll
    for (int i = 0; i < 2; i++)
#pragma unroll
        for (int j = 0; j < 4; j++) acc2[i][j] = 0ull;

    int ar = t >> 2, ac = (t & 3) * 4;

    float4 avR, bvR;
    auto load_tile = [&](int k0) {
        avR = *(const float4*)(A + (size_t)(bm + ar) * K + k0 + ac);
        bvR = *(const float4*)(B + (size_t)(bn + ar) * ldb + k0 + ac);
    };
    auto store_tile = [&]() {
        As[ac + 0][ar] = avR.x; As[ac + 1][ar] = avR.y;
        As[ac + 2][ar] = avR.z; As[ac + 3][ar] = avR.w;
        Bs[ac + 0][ar] = bvR.x; Bs[ac + 1][ar] = bvR.y;
        Bs[ac + 2][ar] = bvR.z; Bs[ac + 3][ar] = bvR.w;
    };

    const int NIT = K / 16;
    load_tile(0);
    store_tile();
    __syncthreads();

    for (int it = 1; it <= NIT; it++) {
        if (it < NIT) load_tile(it * 16);
#pragma unroll
        for (int kk = 0; kk < 16; kk++) {
            const unsigned long long* ap =
                reinterpret_cast<const unsigned long long*>(&As[kk][tm * 4]);
            unsigned long long a2[2] = {ap[0], ap[1]};
            float4 bq = *(const float4*)&Bs[kk][tn * 4];
            unsigned long long b2[4] = {pack2(bq.x, bq.x), pack2(bq.y, bq.y),
                                        pack2(bq.z, bq.z), pack2(bq.w, bq.w)};
#pragma unroll
            for (int i = 0; i < 2; i++)
#pragma unroll
                for (int j = 0; j < 4; j++)
                    fma2(acc2[i][j], a2[i], b2[j]);
        }
        if (it < NIT) {
            __syncthreads();
            store_tile();
            __syncthreads();
        }
    }
#pragma unroll
    for (int i2 = 0; i2 < 2; i2++) {
        float2 u[4];
#pragma unroll
        for (int j = 0; j < 4; j++) u[j] = unpack2(acc2[i2][j]);
#pragma unroll
        for (int half = 0; half < 2; half++) {
            int row = bm + tm * 4 + 2 * i2 + half;
            int p0 = pos[2 * row], p1 = pos[2 * row + 1];
#pragma unroll
            for (int j = 0; j < 4; j++) {
                int col = bn + tn * 4 + j;
                float v = half ? u[j].y : u[j].x;
                v += bias1[col] + bias2[col]
                   + WihFull[(size_t)col * 532 + 512 + p0]
                   + WihFull[(size_t)col * 532 + 522 + p1];
                C[(size_t)row * N + col] = v;
            }
        }
    }
}

__global__ void __launch_bounds__(256) xw_kernel(
    const float* __restrict__ Wih, const float* __restrict__ bih,
    const float* __restrict__ bhh, const int* __restrict__ pos)
{
    xw_body(g_feat, Wih, g_xw, 512, 512, 532, bih, bhh, Wih, pos);
}

// ---------------- persistent LSTM: 32 blocks x 128 threads --------------
__device__ __forceinline__ float sigmoidf_(float x) {
    return 1.0f / (1.0f + __expf(-x));
}

__global__ void __launch_bounds__(128) lstm_kernel(
    const int* __restrict__ done, const float* __restrict__ h0,
    const float* __restrict__ c0, const float* __restrict__ Whh,
    float* __restrict__ out)
{
    int k = blockIdx.x;
    int t = threadIdx.x;
    int lane = t & 31, w = t >> 5;

    __shared__ float whh_s[16][HID];
    __shared__ float h_sh[HID][BBATCH];
    __shared__ float c_s[4][BBATCH];
    __shared__ float gate_s[4][4][BBATCH];
    __shared__ float m_s[BBATCH];

    for (int idx = t; idx < 16 * HID; idx += 128) {
        int r = idx >> 7, j = idx & 127;
        int G = (r >> 2) * HID + k * 4 + (r & 3);
        whh_s[r][j] = Whh[(size_t)G * HID + j];
    }
    c_s[w][lane] = c0[lane * HID + k * 4 + w];
    __stcg(&g_hT[0][(k * 4 + w) * BBATCH + lane], h0[lane * HID + k * 4 + w]);
    __threadfence();
    __syncthreads();
    unsigned target = 32;
    if (t == 0) {
        atomicAdd(&g_bar, 1u);
        while (*((volatile unsigned*)&g_bar) < target) {}
    }
    __syncthreads();

    float h_last = 0.f;
    for (int step = 0; step < TSTEPS; step++) {
        int p = step & 1;
        if (t < 32) m_s[t] = 1.0f - (float)done[step * BBATCH + t];
        __syncthreads();
        for (int idx = t; idx < HID * BBATCH; idx += 128) {
            h_sh[idx >> 5][idx & 31] = __ldcg(&g_hT[p][idx]) * m_s[idx & 31];
        }
        __syncthreads();

        float acc[4];
        const float* xwr = g_xw + (size_t)(step * BBATCH + lane) * 512 + w * HID + k * 4;
#pragma unroll
        for (int ul = 0; ul < 4; ul++) acc[ul] = xwr[ul];
#pragma unroll 4
        for (int j = 0; j < HID; j++) {
            float hv = h_sh[j][lane];
#pragma unroll
            for (int ul = 0; ul < 4; ul++) acc[ul] += hv * whh_s[w * 4 + ul][j];
        }
#pragma unroll
        for (int ul = 0; ul < 4; ul++) gate_s[w][ul][lane] = acc[ul];
        __syncthreads();

        float iv = sigmoidf_(gate_s[0][w][lane]);
        float fv = sigmoidf_(gate_s[1][w][lane]);
        float gv = tanhf(gate_s[2][w][lane]);
        float ov = sigmoidf_(gate_s[3][w][lane]);
        float cc = fv * (c_s[w][lane] * m_s[lane]) + iv * gv;
        c_s[w][lane] = cc;
        float hh = ov * tanhf(cc);
        h_last = hh;
        __stcg(&g_hT[1 - p][(k * 4 + w) * BBATCH + lane], hh);
        g_hs[(size_t)(step * BBATCH + lane) * HID + k * 4 + w] = hh;
        __threadfence();
        __syncthreads();
        target += 32;
        if (t == 0) {
            atomicAdd(&g_bar, 1u);
            while (*((volatile unsigned*)&g_bar) < target) {}
        }
        __syncthreads();
    }
    out[12288 + lane * HID + k * 4 + w] = h_last;
    out[16384 + lane * HID + k * 4 + w] = c_s[w][lane];
}

// ---------------- heads: logits (2048x5) + value (2048x1) ---------------
__global__ void heads_kernel(
    const float* __restrict__ Wp, const float* __restrict__ bp,
    const float* __restrict__ Wv, const float* __restrict__ bv,
    float* __restrict__ out)
{
    int row = blockIdx.x * 8 + threadIdx.y;
    int lane = threadIdx.x;
    const float* h = g_hs + (size_t)row * HID;
    float4 hv = *(const float4*)&h[lane * 4];
    float vals[4] = {hv.x, hv.y, hv.z, hv.w};
    float r[6];
#pragma unroll
    for (int a = 0; a < 5; a++) {
        float s = 0.f;
#pragma unroll
        for (int q = 0; q < 4; q++) s += vals[q] * __ldg(&Wp[(lane * 4 + q) * 5 + a]);
        r[a] = s;
    }
    {
        float s = 0.f;
#pragma unroll
        for (int q = 0; q < 4; q++) s += vals[q] * __ldg(&Wv[lane * 4 + q]);
        r[5] = s;
    }
#pragma unroll
    for (int a = 0; a < 6; a++)
#pragma unroll
        for (int off = 16; off > 0; off >>= 1)
            r[a] += __shfl_xor_sync(0xffffffffu, r[a], off);
    if (lane == 0) {
#pragma unroll
        for (int a = 0; a < 5; a++) out[(size_t)row * 5 + a] = r[a] + __ldg(&bp[a]);
        out[10240 + row] = r[5] + __ldg(&bv[0]);
    }
}

// ---------------- launch ----------------
extern "C" void kernel_launch(void* const* d_in, const int* in_sizes, int n_in,
                              void* d_out, int out_size)
{
    const float* image    = (const float*)d_in[0];
    const int*   position = (const int*)d_in[1];
    const int*   done     = (const int*)d_in[2];
    const float* h0       = (const float*)d_in[3];
    const float* c0       = (const float*)d_in[4];
    const float* W1  = (const float*)d_in[5];
    const float* b1  = (const float*)d_in[6];
    const float* W2  = (const float*)d_in[7];
    const float* b2  = (const float*)d_in[8];
    const float* W3  = (const float*)d_in[9];
    const float* b3  = (const float*)d_in[10];
    const float* Wfc = (const float*)d_in[11];
    const float* bfc = (const float*)d_in[12];
    const float* Wih = (const float*)d_in[13];
    const float* Whh = (const float*)d_in[14];
    const float* bih = (const float*)d_in[15];
    const float* bhh = (const float*)d_in[16];
    const float* Wp  = (const float*)d_in[17];
    const float* bp  = (const float*)d_in[18];
    const float* Wv  = (const float*)d_in[19];
    const float* bv  = (const float*)d_in[20];
    float* out = (float*)d_out;

    // dyn smem: 2 buffers (2*55296) + im2col tables
    const int SM_C2 = 110592 + 512 * 4 + 512;   // 113152
    const int SM_C3 = 110592 + 576 * 4 + 512;   // 113408
    const int SM_FC = 110592;
    cudaFuncSetAttribute(conv2m_kernel, cudaFuncAttributeMaxDynamicSharedMemorySize, SM_C2);
    cudaFuncSetAttribute(conv3m_kernel, cudaFuncAttributeMaxDynamicSharedMemorySize, SM_C3);
    cudaFuncSetAttribute(fcm_kernel,   cudaFuncAttributeMaxDynamicSharedMemorySize, SM_FC);

    // launch #4 (profiled by ncu) = conv2m
    init_kernel<<<1, 32>>>();
    conv1g_kernel<<<819200 / 256, 256>>>(image, W1, b1);
    wsplit_c2_kernel<<<32, 256>>>(W2);
    conv2m_kernel<<<dim3(1, 165888 / 128), 256, SM_C2>>>(b2);
    wsplit_c3_kernel<<<32, 256>>>(W3);
    conv3m_kernel<<<dim3(1, 100352 / 128), 256, SM_C3>>>(b3);
    wsplit_fc_kernel<<<512, 256>>>(Wfc);
    fcm_kernel<<<dim3(8, 2048 / 128), 256, SM_FC>>>(bfc);
    xw_kernel<<<dim3(8, 32), 256>>>(Wih, bih, bhh, position);
    lstm_kernel<<<32, 128>>>(done, h0, c0, Whh, out);
    heads_kernel<<<256, dim3(32, 8)>>>(Wp, bp, Wv, bv, out);
}

// round 15
// speedup vs baseline: 1.5275x; 1.0199x over previous
#include <cuda_runtime.h>
#include <cuda_bf16.h>
#include <cstdint>

// ---------------- problem constants ----------------
#define NIMG 2048          // T*B
#define TSTEPS 64
#define BBATCH 32
#define HID 128

// ---------------- device scratch -------------------
// image + activations stored as bf16 hi/lo split pairs [m][k]
__device__ __nv_bfloat16 g_imgh[NIMG * 21168];
__device__ __nv_bfloat16 g_imgl[NIMG * 21168];
__device__ __nv_bfloat16 g_c1h[NIMG * 400 * 32];
__device__ __nv_bfloat16 g_c1l[NIMG * 400 * 32];
__device__ __nv_bfloat16 g_c2h[NIMG * 81 * 64];
__device__ __nv_bfloat16 g_c2l[NIMG * 81 * 64];
__device__ __nv_bfloat16 g_c3h[NIMG * 3136];
__device__ __nv_bfloat16 g_c3l[NIMG * 3136];
__device__ float g_feat[NIMG * 512];       // fc out (fp32)
__device__ float g_xw[NIMG * 512];         // x@Wih^T + biases + one-hot
__device__ float g_hT[2][HID * BBATCH];
__device__ float g_hs[NIMG * HID];
__device__ unsigned g_bar;

// bf16 hi/lo split weights, transposed to [N][K]
__device__ __nv_bfloat16 g_WfcT_h[512 * 3136];
__device__ __nv_bfloat16 g_WfcT_l[512 * 3136];
__device__ __nv_bfloat16 g_W1T_h[32 * 192];
__device__ __nv_bfloat16 g_W1T_l[32 * 192];
__device__ __nv_bfloat16 g_W2T_h[64 * 512];
__device__ __nv_bfloat16 g_W2T_l[64 * 512];
__device__ __nv_bfloat16 g_W3T_h[64 * 576];
__device__ __nv_bfloat16 g_W3T_l[64 * 576];

__global__ void init_kernel() {
    if (threadIdx.x == 0) g_bar = 0u;
}

// ---------------- packed f32x2 helpers (xw kernel) ----------------
__device__ __forceinline__ void fma2(unsigned long long& d,
                                     unsigned long long a,
                                     unsigned long long b) {
    asm("fma.rn.f32x2 %0, %1, %2, %3;" : "=l"(d) : "l"(a), "l"(b), "l"(d));
}
__device__ __forceinline__ unsigned long long pack2(float lo, float hi) {
    unsigned long long r;
    asm("mov.b64 %0, {%1, %2};" : "=l"(r) : "f"(lo), "f"(hi));
    return r;
}
__device__ __forceinline__ float2 unpack2(unsigned long long v) {
    float2 r;
    asm("mov.b64 {%0, %1}, %2;" : "=f"(r.x), "=f"(r.y) : "l"(v));
    return r;
}
__device__ __forceinline__ uint32_t bf2w(float a, float b) {
    __nv_bfloat162 p = __floats2bfloat162_rn(a, b);
    return *reinterpret_cast<uint32_t*>(&p);
}

// ---------------- warp MMA + async-copy helpers (base-ISA) -----------------
__device__ __forceinline__ uint32_t smem_u32(const void* p) {
    uint32_t a;
    asm("{ .reg .u64 t; cvta.to.shared.u64 t, %1; cvt.u32.u64 %0, t; }"
        : "=r"(a) : "l"(p));
    return a;
}
__device__ __forceinline__ void mma16816(float* c, const uint32_t* a, const uint32_t* b) {
    asm volatile(
        "mma.sync.aligned.m16n8k16.row.col.f32.bf16.bf16.f32 "
        "{%0,%1,%2,%3}, {%4,%5,%6,%7}, {%8,%9}, {%0,%1,%2,%3};"
        : "+f"(c[0]), "+f"(c[1]), "+f"(c[2]), "+f"(c[3])
        : "r"(a[0]), "r"(a[1]), "r"(a[2]), "r"(a[3]), "r"(b[0]), "r"(b[1]));
}
__device__ __forceinline__ void ldsm_x4(uint32_t* r, uint32_t addr) {
    asm volatile("ldmatrix.sync.aligned.m8n8.x4.shared.b16 {%0,%1,%2,%3}, [%4];"
                 : "=r"(r[0]), "=r"(r[1]), "=r"(r[2]), "=r"(r[3]) : "r"(addr));
}
__device__ __forceinline__ void ldsm_x2(uint32_t* r, uint32_t addr) {
    asm volatile("ldmatrix.sync.aligned.m8n8.x2.shared.b16 {%0,%1}, [%2];"
                 : "=r"(r[0]), "=r"(r[1]) : "r"(addr));
}
__device__ __forceinline__ void cpasync16(uint32_t dst, const void* src) {
    asm volatile("cp.async.cg.shared.global [%0], [%1], 16;"
                 :: "r"(dst), "l"(src) : "memory");
}
__device__ __forceinline__ void cpasync8(uint32_t dst, const void* src) {
    asm volatile("cp.async.ca.shared.global [%0], [%1], 8;"
                 :: "r"(dst), "l"(src) : "memory");
}
#define CP_COMMIT() asm volatile("cp.async.commit_group;" ::: "memory")
#define CP_WAIT1()  asm volatile("cp.async.wait_group 1;" ::: "memory")
#define CP_WAIT0()  asm volatile("cp.async.wait_group 0;" ::: "memory")

// ---------------- image fp32 -> bf16 hi/lo split ----------------
__global__ void imgsplit_kernel(const float* __restrict__ img) {
    const int total4 = NIMG * 21168 / 4;
    for (int i = blockIdx.x * blockDim.x + threadIdx.x; i < total4;
         i += gridDim.x * blockDim.x) {
        float4 v = *(const float4*)(img + (size_t)i * 4);
        float h0 = __bfloat162float(__float2bfloat16(v.x));
        float h1 = __bfloat162float(__float2bfloat16(v.y));
        float h2 = __bfloat162float(__float2bfloat16(v.z));
        float h3 = __bfloat162float(__float2bfloat16(v.w));
        uint2 wh = {bf2w(v.x, v.y), bf2w(v.z, v.w)};
        uint2 wl = {bf2w(v.x - h0, v.y - h1), bf2w(v.z - h2, v.w - h3)};
        *(uint2*)(g_imgh + (size_t)i * 4) = wh;
        *(uint2*)(g_imgl + (size_t)i * 4) = wl;
    }
}

// ---------------- weight pre-transpose + bf16 hi/lo split -----------------
template<int K, int N>
__device__ __forceinline__ void wsplit_body(const float* __restrict__ W,
                                            __nv_bfloat16* __restrict__ Th,
                                            __nv_bfloat16* __restrict__ Tl) {
    int total = K * N;
    for (int idx = blockIdx.x * blockDim.x + threadIdx.x; idx < total;
         idx += gridDim.x * blockDim.x) {
        int n = idx / K, k = idx - n * K;
        float x = __ldg(&W[(size_t)k * N + n]);
        __nv_bfloat16 h = __float2bfloat16(x);
        float r = x - __bfloat162float(h);
        Th[idx] = h;
        Tl[idx] = __float2bfloat16(r);
    }
}
__global__ void wsplit_fc_kernel(const float* __restrict__ W) {
    wsplit_body<3136, 512>(W, g_WfcT_h, g_WfcT_l);
}
__global__ void wsplit_c1_kernel(const float* __restrict__ W) {
    wsplit_body<192, 32>(W, g_W1T_h, g_W1T_l);
}
__global__ void wsplit_c2_kernel(const float* __restrict__ W) {
    wsplit_body<512, 64>(W, g_W2T_h, g_W2T_l);
}
__global__ void wsplit_c3_kernel(const float* __restrict__ W) {
    wsplit_body<576, 64>(W, g_W3T_h, g_W3T_l);
}

// ============ HMMA bf16x3 GEMM, cp.async double-buffered ============
// A bf16 hi/lo pair [m][k] (im2col-gatherable); B^T bf16 hi/lo [N][K].
// CTA: 128(M) x BN(N); 8 warps as WM(M) x (8/WM)(N); m16n8k16; 3 split terms.
// GRAN: A-staging async-copy granularity in bytes (16, or 8 for CI=3 im2col).
template<int BN, int WM, int NTOT, int K, int IM2COL, int P, int PW, int S,
         int IW, int CI, int KW, int GRAN, int OUTBF>
__device__ void mgemm_body(const __nv_bfloat16* __restrict__ Ah,
                           const __nv_bfloat16* __restrict__ Al,
                           const __nv_bfloat16* __restrict__ BhT,
                           const __nv_bfloat16* __restrict__ BlT,
                           const float* __restrict__ bias,
                           __nv_bfloat16* __restrict__ outh,
                           __nv_bfloat16* __restrict__ outl,
                           float* __restrict__ outf)
{
    extern __shared__ char smem[];
    constexpr int WN  = 8 / WM;                   // warps along N
    constexpr int MT  = 128 / (WM * 16);          // m16 tiles per warp
    constexpr int LDAB = 144;                     // bytes per smem row (72 bf16)
    constexpr int A_BYTES = 128 * LDAB;
    constexpr int B_BYTES = BN * LDAB;
    constexpr int BUF_BYTES = 2 * A_BYTES + 2 * B_BYTES;
    constexpr int OFF_AH  = 0;
    constexpr int OFF_AL  = A_BYTES;
    constexpr int OFF_BH  = 2 * A_BYTES;
    constexpr int OFF_BL  = 2 * A_BYTES + B_BYTES;
    constexpr int OFF_KO  = 2 * BUF_BYTES;
    constexpr int OFF_ROW = OFF_KO + (IM2COL ? K * 4 : 0);

    const int t = threadIdx.x;
    const int wid = t >> 5, L = t & 31;
    const int wm = wid / WN, wn = wid % WN;
    const int g = L >> 2, tc = L & 3;
    const int bm = blockIdx.y * 128;
    const int bn = blockIdx.x * BN;
    uint32_t sbase = smem_u32(smem);
    int* s_koff = (int*)(smem + OFF_KO);
    int* s_row  = (int*)(smem + OFF_ROW);

    if (IM2COL) {
        for (int i = t; i < K; i += 256) {
            int ky = i / (KW * CI);
            int r  = i - ky * (KW * CI);
            int kx = r / CI;
            int ci = r - kx * CI;
            s_koff[i] = (ky * IW + kx) * CI + ci;
        }
        if (t < 128) {
            int m = bm + t;
            int n = m / P;
            int p = m - n * P;
            int py = p / PW;
            int px = p - py * PW;
            s_row[t] = n * (IW * IW * CI) + (py * S * IW + px * S) * CI;
        }
        __syncthreads();
    }

    // per-lane ldmatrix offsets (within a buffer)
    const uint32_t aoffL = (uint32_t)((wm * (128 / WM) + (L & 15)) * LDAB + (L >> 4) * 16);
    const uint32_t boffL = (uint32_t)((wn * 32 + (L & 7)) * LDAB + ((L >> 3) & 1) * 16);

    // im2col 16B-segment geometry (GRAN=16 path)
    constexpr int UPS = (IM2COL && CI == 32) ? 4 : 8;

    auto stage = [&](int ch, int buf) {
        const int k0 = ch * 64;
        const uint32_t sb = sbase + buf * BUF_BYTES;
        if (GRAN == 16) {
            for (int u = t; u < 1024; u += 256) {
                int r = u >> 3, i = u & 7;
                int seg = i / UPS, isg = i - seg * UPS;
                size_t src;
                if (IM2COL) src = (size_t)s_row[r] + s_koff[k0 + seg * CI] + isg * 8;
                else        src = (size_t)(bm + r) * K + k0 + i * 8;
                cpasync16(sb + OFF_AH + r * LDAB + i * 16, Ah + src);
                cpasync16(sb + OFF_AL + r * LDAB + i * 16, Al + src);
            }
        } else {   // GRAN == 8: per 4-element k-group (contiguous for CI=3)
            for (int u = t; u < 2048; u += 256) {
                int r = u >> 4, i = u & 15;
                size_t src = (size_t)s_row[r] + s_koff[k0 + i * 4];
                cpasync8(sb + OFF_AH + r * LDAB + i * 8, Ah + src);
                cpasync8(sb + OFF_AL + r * LDAB + i * 8, Al + src);
            }
        }
        for (int e = t; e < BN * 8; e += 256) {
            int n = e >> 3, i = e & 7;
            size_t src = (size_t)(bn + n) * K + k0 + i * 8;
            cpasync16(sb + OFF_BH + n * LDAB + i * 16, BhT + src);
            cpasync16(sb + OFF_BL + n * LDAB + i * 16, BlT + src);
        }
    };

    float acc[MT][4][4];
#pragma unroll
    for (int i = 0; i < MT; i++)
#pragma unroll
        for (int j = 0; j < 4; j++)
#pragma unroll
            for (int q = 0; q < 4; q++) acc[i][j][q] = 0.f;

    constexpr int NCH = K / 64;
    stage(0, 0);
    CP_COMMIT();

    for (int ch = 0; ch < NCH; ch++) {
        if (ch + 1 < NCH) {
            stage(ch + 1, (ch + 1) & 1);
            CP_COMMIT();
            CP_WAIT1();
        } else {
            CP_WAIT0();
        }
        __syncthreads();

        const uint32_t sb = sbase + (uint32_t)(ch & 1) * BUF_BYTES;
        const uint32_t aH = sb + OFF_AH + aoffL;
        const uint32_t aL = sb + OFF_AL + aoffL;
        const uint32_t bH = sb + OFF_BH + boffL;
        const uint32_t bL = sb + OFF_BL + boffL;

#pragma unroll
        for (int ks = 0; ks < 4; ks++) {
            uint32_t ah[MT][4], al[MT][4], bh[4][2], bl[4][2];
#pragma unroll
            for (int mt = 0; mt < MT; mt++) {
                ldsm_x4(ah[mt], aH + mt * 16 * LDAB + ks * 32);
                ldsm_x4(al[mt], aL + mt * 16 * LDAB + ks * 32);
            }
#pragma unroll
            for (int nt = 0; nt < 4; nt++) {
                ldsm_x2(bh[nt], bH + nt * 8 * LDAB + ks * 32);
                ldsm_x2(bl[nt], bL + nt * 8 * LDAB + ks * 32);
            }
#pragma unroll
            for (int mt = 0; mt < MT; mt++)
#pragma unroll
                for (int nt = 0; nt < 4; nt++) {
                    mma16816(acc[mt][nt], ah[mt], bh[nt]);
                    mma16816(acc[mt][nt], ah[mt], bl[nt]);
                    mma16816(acc[mt][nt], al[mt], bh[nt]);
                }
        }
        __syncthreads();
    }

    // ---- epilogue: c-frag layout, bias + relu; bf16-split or fp32 out ----
#pragma unroll
    for (int mt = 0; mt < MT; mt++) {
#pragma unroll
        for (int nt = 0; nt < 4; nt++) {
            int col = bn + wn * 32 + nt * 8 + tc * 2;
            float b0 = __ldg(&bias[col]);
            float b1 = __ldg(&bias[col + 1]);
            int r0 = bm + wm * (128 / WM) + mt * 16 + g;
            float v00 = fmaxf(acc[mt][nt][0] + b0, 0.f);
            float v01 = fmaxf(acc[mt][nt][1] + b1, 0.f);
            float v10 = fmaxf(acc[mt][nt][2] + b0, 0.f);
            float v11 = fmaxf(acc[mt][nt][3] + b1, 0.f);
            if (OUTBF) {
                float h00 = __bfloat162float(__float2bfloat16(v00));
                float h01 = __bfloat162float(__float2bfloat16(v01));
                float h10 = __bfloat162float(__float2bfloat16(v10));
                float h11 = __bfloat162float(__float2bfloat16(v11));
                *(uint32_t*)&outh[(size_t)r0 * NTOT + col]       = bf2w(v00, v01);
                *(uint32_t*)&outl[(size_t)r0 * NTOT + col]       = bf2w(v00 - h00, v01 - h01);
                *(uint32_t*)&outh[(size_t)(r0 + 8) * NTOT + col] = bf2w(v10, v11);
                *(uint32_t*)&outl[(size_t)(r0 + 8) * NTOT + col] = bf2w(v10 - h10, v11 - h11);
            } else {
                float2 v0 = {v00, v01}, v1 = {v10, v11};
                *(float2*)&outf[(size_t)r0 * NTOT + col]       = v0;
                *(float2*)&outf[(size_t)(r0 + 8) * NTOT + col] = v1;
            }
        }
    }
}

// conv1: A = im2col(img bf16 pair), M=819200, K=192, N=32 (BN=32, WM=8, GRAN=8)
__global__ void __launch_bounds__(256) conv1m_kernel(const float* __restrict__ bias) {
    mgemm_body<32, 8, 32, 192, 1, 400, 20, 4, 84, 3, 8, 8, 1>(
        g_imgh, g_imgl, g_W1T_h, g_W1T_l, bias, g_c1h, g_c1l, nullptr);
}
// conv2: A = im2col(c1 bf16 pair), M=165888, K=512, N=64
__global__ void __launch_bounds__(256) conv2m_kernel(const float* __restrict__ bias) {
    mgemm_body<64, 4, 64, 512, 1, 81, 9, 2, 20, 32, 4, 16, 1>(
        g_c1h, g_c1l, g_W2T_h, g_W2T_l, bias, g_c2h, g_c2l, nullptr);
}
// conv3: A = im2col(c2 bf16 pair), M=100352, K=576, N=64
__global__ void __launch_bounds__(256) conv3m_kernel(const float* __restrict__ bias) {
    mgemm_body<64, 4, 64, 576, 1, 49, 7, 1, 9, 64, 3, 16, 1>(
        g_c2h, g_c2l, g_W3T_h, g_W3T_l, bias, g_c3h, g_c3l, nullptr);
}
// fc: A = c3 bf16 pair, M=2048, K=3136, N=512 -> fp32
__global__ void __launch_bounds__(256) fcm_kernel(const float* __restrict__ bias) {
    mgemm_body<64, 4, 512, 3136, 0, 1, 1, 1, 1, 1, 1, 16, 0>(
        g_c3h, g_c3l, g_WfcT_h, g_WfcT_l, bias, nullptr, nullptr, g_feat);
}

// ---------------- xw: SGEMM 64x64x16 f32x2 (EPI: biases + one-hot) --------
__device__ __forceinline__ void xw_body(
    const float* __restrict__ A, const float* __restrict__ B,
    float* __restrict__ C, int N, int K, int ldb,
    const float* __restrict__ bias1, const float* __restrict__ bias2,
    const float* __restrict__ WihFull, const int* __restrict__ pos)
{
    __shared__ __align__(16) float As[16][68];
    __shared__ __align__(16) float Bs[16][68];
    int bm = blockIdx.y * 64, bn = blockIdx.x * 64;
    int t = threadIdx.x;
    int tm = t >> 4, tn = t & 15;

    unsigned long long acc2[2][4];
#pragma unroll
    for (int i = 0; i < 2; i++)
#pragma unroll
        for (int j = 0; j < 4; j++) acc2[i][j] = 0ull;

    int ar = t >> 2, ac = (t & 3) * 4;

    float4 avR, bvR;
    auto load_tile = [&](int k0) {
        avR = *(const float4*)(A + (size_t)(bm + ar) * K + k0 + ac);
        bvR = *(const float4*)(B + (size_t)(bn + ar) * ldb + k0 + ac);
    };
    auto store_tile = [&]() {
        As[ac + 0][ar] = avR.x; As[ac + 1][ar] = avR.y;
        As[ac + 2][ar] = avR.z; As[ac + 3][ar] = avR.w;
        Bs[ac + 0][ar] = bvR.x; Bs[ac + 1][ar] = bvR.y;
        Bs[ac + 2][ar] = bvR.z; Bs[ac + 3][ar] = bvR.w;
    };

    const int NIT = K / 16;
    load_tile(0);
    store_tile();
    __syncthreads();

    for (int it = 1; it <= NIT; it++) {
        if (it < NIT) load_tile(it * 16);
#pragma unroll
        for (int kk = 0; kk < 16; kk++) {
            const unsigned long long* ap =
                reinterpret_cast<const unsigned long long*>(&As[kk][tm * 4]);
            unsigned long long a2[2] = {ap[0], ap[1]};
            float4 bq = *(const float4*)&Bs[kk][tn * 4];
            unsigned long long b2[4] = {pack2(bq.x, bq.x), pack2(bq.y, bq.y),
                                        pack2(bq.z, bq.z), pack2(bq.w, bq.w)};
#pragma unroll
            for (int i = 0; i < 2; i++)
#pragma unroll
                for (int j = 0; j < 4; j++)
                    fma2(acc2[i][j], a2[i], b2[j]);
        }
        if (it < NIT) {
            __syncthreads();
            store_tile();
            __syncthreads();
        }
    }
#pragma unroll
    for (int i2 = 0; i2 < 2; i2++) {
        float2 u[4];
#pragma unroll
        for (int j = 0; j < 4; j++) u[j] = unpack2(acc2[i2][j]);
#pragma unroll
        for (int half = 0; half < 2; half++) {
            int row = bm + tm * 4 + 2 * i2 + half;
            int p0 = pos[2 * row], p1 = pos[2 * row + 1];
#pragma unroll
            for (int j = 0; j < 4; j++) {
                int col = bn + tn * 4 + j;
                float v = half ? u[j].y : u[j].x;
                v += bias1[col] + bias2[col]
                   + WihFull[(size_t)col * 532 + 512 + p0]
                   + WihFull[(size_t)col * 532 + 522 + p1];
                C[(size_t)row * N + col] = v;
            }
        }
    }
}

__global__ void __launch_bounds__(256) xw_kernel(
    const float* __restrict__ Wih, const float* __restrict__ bih,
    const float* __restrict__ bhh, const int* __restrict__ pos)
{
    xw_body(g_feat, Wih, g_xw, 512, 512, 532, bih, bhh, Wih, pos);
}

// ---------------- persistent LSTM: 32 blocks x 128 threads --------------
__device__ __forceinline__ float sigmoidf_(float x) {
    return 1.0f / (1.0f + __expf(-x));
}

__global__ void __launch_bounds__(128) lstm_kernel(
    const int* __restrict__ done, const float* __restrict__ h0,
    const float* __restrict__ c0, const float* __restrict__ Whh,
    float* __restrict__ out)
{
    int k = blockIdx.x;
    int t = threadIdx.x;
    int lane = t & 31, w = t >> 5;

    __shared__ float whh_s[16][HID];
    __shared__ float h_sh[HID][BBATCH];
    __shared__ float c_s[4][BBATCH];
    __shared__ float gate_s[4][4][BBATCH];
    __shared__ float m_s[BBATCH];

    for (int idx = t; idx < 16 * HID; idx += 128) {
        int r = idx >> 7, j = idx & 127;
        int G = (r >> 2) * HID + k * 4 + (r & 3);
        whh_s[r][j] = Whh[(size_t)G * HID + j];
    }
    c_s[w][lane] = c0[lane * HID + k * 4 + w];
    __stcg(&g_hT[0][(k * 4 + w) * BBATCH + lane], h0[lane * HID + k * 4 + w]);
    __threadfence();
    __syncthreads();
    unsigned target = 32;
    if (t == 0) {
        atomicAdd(&g_bar, 1u);
        while (*((volatile unsigned*)&g_bar) < target) {}
    }
    __syncthreads();

    float h_last = 0.f;
    for (int step = 0; step < TSTEPS; step++) {
        int p = step & 1;
        if (t < 32) m_s[t] = 1.0f - (float)done[step * BBATCH + t];
        __syncthreads();
        for (int idx = t; idx < HID * BBATCH; idx += 128) {
            h_sh[idx >> 5][idx & 31] = __ldcg(&g_hT[p][idx]) * m_s[idx & 31];
        }
        __syncthreads();

        float acc[4];
        const float* xwr = g_xw + (size_t)(step * BBATCH + lane) * 512 + w * HID + k * 4;
#pragma unroll
        for (int ul = 0; ul < 4; ul++) acc[ul] = xwr[ul];
#pragma unroll 4
        for (int j = 0; j < HID; j++) {
            float hv = h_sh[j][lane];
#pragma unroll
            for (int ul = 0; ul < 4; ul++) acc[ul] += hv * whh_s[w * 4 + ul][j];
        }
#pragma unroll
        for (int ul = 0; ul < 4; ul++) gate_s[w][ul][lane] = acc[ul];
        __syncthreads();

        float iv = sigmoidf_(gate_s[0][w][lane]);
        float fv = sigmoidf_(gate_s[1][w][lane]);
        float gv = tanhf(gate_s[2][w][lane]);
        float ov = sigmoidf_(gate_s[3][w][lane]);
        float cc = fv * (c_s[w][lane] * m_s[lane]) + iv * gv;
        c_s[w][lane] = cc;
        float hh = ov * tanhf(cc);
        h_last = hh;
        __stcg(&g_hT[1 - p][(k * 4 + w) * BBATCH + lane], hh);
        g_hs[(size_t)(step * BBATCH + lane) * HID + k * 4 + w] = hh;
        __threadfence();
        __syncthreads();
        target += 32;
        if (t == 0) {
            atomicAdd(&g_bar, 1u);
            while (*((volatile unsigned*)&g_bar) < target) {}
        }
        __syncthreads();
    }
    out[12288 + lane * HID + k * 4 + w] = h_last;
    out[16384 + lane * HID + k * 4 + w] = c_s[w][lane];
}

// ---------------- heads: logits (2048x5) + value (2048x1) ---------------
__global__ void heads_kernel(
    const float* __restrict__ Wp, const float* __restrict__ bp,
    const float* __restrict__ Wv, const float* __restrict__ bv,
    float* __restrict__ out)
{
    int row = blockIdx.x * 8 + threadIdx.y;
    int lane = threadIdx.x;
    const float* h = g_hs + (size_t)row * HID;
    float4 hv = *(const float4*)&h[lane * 4];
    float vals[4] = {hv.x, hv.y, hv.z, hv.w};
    float r[6];
#pragma unroll
    for (int a = 0; a < 5; a++) {
        float s = 0.f;
#pragma unroll
        for (int q = 0; q < 4; q++) s += vals[q] * __ldg(&Wp[(lane * 4 + q) * 5 + a]);
        r[a] = s;
    }
    {
        float s = 0.f;
#pragma unroll
        for (int q = 0; q < 4; q++) s += vals[q] * __ldg(&Wv[lane * 4 + q]);
        r[5] = s;
    }
#pragma unroll
    for (int a = 0; a < 6; a++)
#pragma unroll
        for (int off = 16; off > 0; off >>= 1)
            r[a] += __shfl_xor_sync(0xffffffffu, r[a], off);
    if (lane == 0) {
#pragma unroll
        for (int a = 0; a < 5; a++) out[(size_t)row * 5 + a] = r[a] + __ldg(&bp[a]);
        out[10240 + row] = r[5] + __ldg(&bv[0]);
    }
}

// ---------------- launch ----------------
extern "C" void kernel_launch(void* const* d_in, const int* in_sizes, int n_in,
                              void* d_out, int out_size)
{
    const float* image    = (const float*)d_in[0];
    const int*   position = (const int*)d_in[1];
    const int*   done     = (const int*)d_in[2];
    const float* h0       = (const float*)d_in[3];
    const float* c0       = (const float*)d_in[4];
    const float* W1  = (const float*)d_in[5];
    const float* b1  = (const float*)d_in[6];
    const float* W2  = (const float*)d_in[7];
    const float* b2  = (const float*)d_in[8];
    const float* W3  = (const float*)d_in[9];
    const float* b3  = (const float*)d_in[10];
    const float* Wfc = (const float*)d_in[11];
    const float* bfc = (const float*)d_in[12];
    const float* Wih = (const float*)d_in[13];
    const float* Whh = (const float*)d_in[14];
    const float* bih = (const float*)d_in[15];
    const float* bhh = (const float*)d_in[16];
    const float* Wp  = (const float*)d_in[17];
    const float* bp  = (const float*)d_in[18];
    const float* Wv  = (const float*)d_in[19];
    const float* bv  = (const float*)d_in[20];
    float* out = (float*)d_out;

    // dyn smem sizes
    const int SM_C1 = 2 * (2 * 128 * 144 + 2 * 32 * 144) + 192 * 4 + 512;   // 93440
    const int SM_C2 = 110592 + 512 * 4 + 512;
    const int SM_C3 = 110592 + 576 * 4 + 512;
    const int SM_FC = 110592;
    cudaFuncSetAttribute(conv1m_kernel, cudaFuncAttributeMaxDynamicSharedMemorySize, SM_C1);
    cudaFuncSetAttribute(conv2m_kernel, cudaFuncAttributeMaxDynamicSharedMemorySize, SM_C2);
    cudaFuncSetAttribute(conv3m_kernel, cudaFuncAttributeMaxDynamicSharedMemorySize, SM_C3);
    cudaFuncSetAttribute(fcm_kernel,   cudaFuncAttributeMaxDynamicSharedMemorySize, SM_FC);

    // launch #4 (profiled by ncu) = conv1m
    init_kernel<<<1, 32>>>();
    imgsplit_kernel<<<2048, 256>>>(image);
    wsplit_c1_kernel<<<8, 256>>>(W1);
    conv1m_kernel<<<dim3(1, 819200 / 128), 256, SM_C1>>>(b1);
    wsplit_c2_kernel<<<32, 256>>>(W2);
    conv2m_kernel<<<dim3(1, 165888 / 128), 256, SM_C2>>>(b2);
    wsplit_c3_kernel<<<32, 256>>>(W3);
    conv3m_kernel<<<dim3(1, 100352 / 128), 256, SM_C3>>>(b3);
    wsplit_fc_kernel<<<512, 256>>>(Wfc);
    fcm_kernel<<<dim3(8, 2048 / 128), 256, SM_FC>>>(bfc);
    xw_kernel<<<dim3(8, 32), 256>>>(Wih, bih, bhh, position);
    lstm_kernel<<<32, 128>>>(done, h0, c0, Whh, out);
    heads_kernel<<<256, dim3(32, 8)>>>(Wp, bp, Wv, bv, out);
}

// round 16
// speedup vs baseline: 1.5866x; 1.0387x over previous
#include <cuda_runtime.h>
#include <cuda_bf16.h>
#include <cstdint>

// ---------------- problem constants ----------------
#define NIMG 2048          // T*B
#define TSTEPS 64
#define BBATCH 32
#define HID 128

// ---------------- device scratch -------------------
// image + activations stored as bf16 hi/lo split pairs [m][k]
__device__ __nv_bfloat16 g_imgh[NIMG * 21168 + 64];
__device__ __nv_bfloat16 g_imgl[NIMG * 21168 + 64];
__device__ __nv_bfloat16 g_c1h[NIMG * 400 * 32];
__device__ __nv_bfloat16 g_c1l[NIMG * 400 * 32];
__device__ __nv_bfloat16 g_c2h[NIMG * 81 * 64];
__device__ __nv_bfloat16 g_c2l[NIMG * 81 * 64];
__device__ __nv_bfloat16 g_c3h[NIMG * 3136];
__device__ __nv_bfloat16 g_c3l[NIMG * 3136];
__device__ float g_feat[NIMG * 512];       // fc out (fp32)
__device__ float g_xw[NIMG * 512];         // x@Wih^T + biases + one-hot
__device__ float g_hT[2][HID * BBATCH];
__device__ float g_hs[NIMG * HID];
__device__ unsigned g_wf[32 * 32];         // per-CTA lstm barrier flags (128B apart)

// bf16 hi/lo split weights, transposed to [N][K]
__device__ __nv_bfloat16 g_WfcT_h[512 * 3136];
__device__ __nv_bfloat16 g_WfcT_l[512 * 3136];
__device__ __nv_bfloat16 g_W1T_h[32 * 192];
__device__ __nv_bfloat16 g_W1T_l[32 * 192];
__device__ __nv_bfloat16 g_W2T_h[64 * 512];
__device__ __nv_bfloat16 g_W2T_l[64 * 512];
__device__ __nv_bfloat16 g_W3T_h[64 * 576];
__device__ __nv_bfloat16 g_W3T_l[64 * 576];

__global__ void init_kernel() {
    if (threadIdx.x < 32) g_wf[threadIdx.x * 32] = 0u;
}

// ---------------- packed f32x2 helpers (xw kernel) ----------------
__device__ __forceinline__ void fma2(unsigned long long& d,
                                     unsigned long long a,
                                     unsigned long long b) {
    asm("fma.rn.f32x2 %0, %1, %2, %3;" : "=l"(d) : "l"(a), "l"(b), "l"(d));
}
__device__ __forceinline__ unsigned long long pack2(float lo, float hi) {
    unsigned long long r;
    asm("mov.b64 %0, {%1, %2};" : "=l"(r) : "f"(lo), "f"(hi));
    return r;
}
__device__ __forceinline__ float2 unpack2(unsigned long long v) {
    float2 r;
    asm("mov.b64 {%0, %1}, %2;" : "=f"(r.x), "=f"(r.y) : "l"(v));
    return r;
}
__device__ __forceinline__ uint32_t bf2w(float a, float b) {
    __nv_bfloat162 p = __floats2bfloat162_rn(a, b);
    return *reinterpret_cast<uint32_t*>(&p);
}

// ---------------- warp MMA + async-copy helpers (base-ISA) -----------------
__device__ __forceinline__ uint32_t smem_u32(const void* p) {
    uint32_t a;
    asm("{ .reg .u64 t; cvta.to.shared.u64 t, %1; cvt.u32.u64 %0, t; }"
        : "=r"(a) : "l"(p));
    return a;
}
__device__ __forceinline__ void mma16816(float* c, const uint32_t* a, const uint32_t* b) {
    asm volatile(
        "mma.sync.aligned.m16n8k16.row.col.f32.bf16.bf16.f32 "
        "{%0,%1,%2,%3}, {%4,%5,%6,%7}, {%8,%9}, {%0,%1,%2,%3};"
        : "+f"(c[0]), "+f"(c[1]), "+f"(c[2]), "+f"(c[3])
        : "r"(a[0]), "r"(a[1]), "r"(a[2]), "r"(a[3]), "r"(b[0]), "r"(b[1]));
}
__device__ __forceinline__ void ldsm_x4(uint32_t* r, uint32_t addr) {
    asm volatile("ldmatrix.sync.aligned.m8n8.x4.shared.b16 {%0,%1,%2,%3}, [%4];"
                 : "=r"(r[0]), "=r"(r[1]), "=r"(r[2]), "=r"(r[3]) : "r"(addr));
}
__device__ __forceinline__ void ldsm_x2(uint32_t* r, uint32_t addr) {
    asm volatile("ldmatrix.sync.aligned.m8n8.x2.shared.b16 {%0,%1}, [%2];"
                 : "=r"(r[0]), "=r"(r[1]) : "r"(addr));
}
__device__ __forceinline__ void cpasync16(uint32_t dst, const void* src) {
    asm volatile("cp.async.cg.shared.global [%0], [%1], 16;"
                 :: "r"(dst), "l"(src) : "memory");
}
__device__ __forceinline__ void cpasync8(uint32_t dst, const void* src) {
    asm volatile("cp.async.ca.shared.global [%0], [%1], 8;"
                 :: "r"(dst), "l"(src) : "memory");
}
#define CP_COMMIT() asm volatile("cp.async.commit_group;" ::: "memory")
#define CP_WAIT1()  asm volatile("cp.async.wait_group 1;" ::: "memory")
#define CP_WAIT0()  asm volatile("cp.async.wait_group 0;" ::: "memory")

// lstm barrier primitives (release/acquire, no membar)
__device__ __forceinline__ void red_rel(unsigned* p) {
    asm volatile("red.release.gpu.global.add.u32 [%0], 1;" :: "l"(p) : "memory");
}
__device__ __forceinline__ unsigned ld_acq(const unsigned* p) {
    unsigned v;
    asm volatile("ld.acquire.gpu.global.u32 %0, [%1];" : "=r"(v) : "l"(p) : "memory");
    return v;
}

// ---------------- image fp32 -> bf16 hi/lo split ----------------
__global__ void imgsplit_kernel(const float* __restrict__ img) {
    const int total4 = NIMG * 21168 / 4;
    for (int i = blockIdx.x * blockDim.x + threadIdx.x; i < total4;
         i += gridDim.x * blockDim.x) {
        float4 v = *(const float4*)(img + (size_t)i * 4);
        float h0 = __bfloat162float(__float2bfloat16(v.x));
        float h1 = __bfloat162float(__float2bfloat16(v.y));
        float h2 = __bfloat162float(__float2bfloat16(v.z));
        float h3 = __bfloat162float(__float2bfloat16(v.w));
        uint2 wh = {bf2w(v.x, v.y), bf2w(v.z, v.w)};
        uint2 wl = {bf2w(v.x - h0, v.y - h1), bf2w(v.z - h2, v.w - h3)};
        *(uint2*)(g_imgh + (size_t)i * 4) = wh;
        *(uint2*)(g_imgl + (size_t)i * 4) = wl;
    }
}

// ---------------- weight pre-transpose + bf16 hi/lo split -----------------
template<int K, int N>
__device__ __forceinline__ void wsplit_body(const float* __restrict__ W,
                                            __nv_bfloat16* __restrict__ Th,
                                            __nv_bfloat16* __restrict__ Tl) {
    int total = K * N;
    for (int idx = blockIdx.x * blockDim.x + threadIdx.x; idx < total;
         idx += gridDim.x * blockDim.x) {
        int n = idx / K, k = idx - n * K;
        float x = __ldg(&W[(size_t)k * N + n]);
        __nv_bfloat16 h = __float2bfloat16(x);
        float r = x - __bfloat162float(h);
        Th[idx] = h;
        Tl[idx] = __float2bfloat16(r);
    }
}
__global__ void wsplit_fc_kernel(const float* __restrict__ W) {
    wsplit_body<3136, 512>(W, g_WfcT_h, g_WfcT_l);
}
__global__ void wsplit_c1_kernel(const float* __restrict__ W) {
    wsplit_body<192, 32>(W, g_W1T_h, g_W1T_l);
}
__global__ void wsplit_c2_kernel(const float* __restrict__ W) {
    wsplit_body<512, 64>(W, g_W2T_h, g_W2T_l);
}
__global__ void wsplit_c3_kernel(const float* __restrict__ W) {
    wsplit_body<576, 64>(W, g_W3T_h, g_W3T_l);
}

// ============ HMMA bf16x3 GEMM, cp.async double-buffered ============
template<int BN, int WM, int NTOT, int K, int IM2COL, int P, int PW, int S,
         int IW, int CI, int KW, int GRAN, int OUTBF>
__device__ void mgemm_body(const __nv_bfloat16* __restrict__ Ah,
                           const __nv_bfloat16* __restrict__ Al,
                           const __nv_bfloat16* __restrict__ BhT,
                           const __nv_bfloat16* __restrict__ BlT,
                           const float* __restrict__ bias,
                           __nv_bfloat16* __restrict__ outh,
                           __nv_bfloat16* __restrict__ outl,
                           float* __restrict__ outf)
{
    extern __shared__ char smem[];
    constexpr int WN  = 8 / WM;
    constexpr int MT  = 128 / (WM * 16);
    constexpr int LDAB = 144;
    constexpr int A_BYTES = 128 * LDAB;
    constexpr int B_BYTES = BN * LDAB;
    constexpr int BUF_BYTES = 2 * A_BYTES + 2 * B_BYTES;
    constexpr int OFF_AH  = 0;
    constexpr int OFF_AL  = A_BYTES;
    constexpr int OFF_BH  = 2 * A_BYTES;
    constexpr int OFF_BL  = 2 * A_BYTES + B_BYTES;
    constexpr int OFF_KO  = 2 * BUF_BYTES;
    constexpr int OFF_ROW = OFF_KO + (IM2COL ? K * 4 : 0);

    const int t = threadIdx.x;
    const int wid = t >> 5, L = t & 31;
    const int wm = wid / WN, wn = wid % WN;
    const int g = L >> 2, tc = L & 3;
    const int bm = blockIdx.y * 128;
    const int bn = blockIdx.x * BN;
    uint32_t sbase = smem_u32(smem);
    int* s_koff = (int*)(smem + OFF_KO);
    int* s_row  = (int*)(smem + OFF_ROW);

    if (IM2COL) {
        for (int i = t; i < K; i += 256) {
            int ky = i / (KW * CI);
            int r  = i - ky * (KW * CI);
            int kx = r / CI;
            int ci = r - kx * CI;
            s_koff[i] = (ky * IW + kx) * CI + ci;
        }
        if (t < 128) {
            int m = bm + t;
            int n = m / P;
            int p = m - n * P;
            int py = p / PW;
            int px = p - py * PW;
            s_row[t] = n * (IW * IW * CI) + (py * S * IW + px * S) * CI;
        }
        __syncthreads();
    }

    const uint32_t aoffL = (uint32_t)((wm * (128 / WM) + (L & 15)) * LDAB + (L >> 4) * 16);
    const uint32_t boffL = (uint32_t)((wn * 32 + (L & 7)) * LDAB + ((L >> 3) & 1) * 16);

    constexpr int UPS = (IM2COL && CI == 32) ? 4 : 8;

    auto stage = [&](int ch, int buf) {
        const int k0 = ch * 64;
        const uint32_t sb = sbase + buf * BUF_BYTES;
        if (GRAN == 16) {
            for (int u = t; u < 1024; u += 256) {
                int r = u >> 3, i = u & 7;
                int seg = i / UPS, isg = i - seg * UPS;
                size_t src;
                if (IM2COL) src = (size_t)s_row[r] + s_koff[k0 + seg * CI] + isg * 8;
                else        src = (size_t)(bm + r) * K + k0 + i * 8;
                cpasync16(sb + OFF_AH + r * LDAB + i * 16, Ah + src);
                cpasync16(sb + OFF_AL + r * LDAB + i * 16, Al + src);
            }
        } else {
            for (int u = t; u < 2048; u += 256) {
                int r = u >> 4, i = u & 15;
                size_t src = (size_t)s_row[r] + s_koff[k0 + i * 4];
                cpasync8(sb + OFF_AH + r * LDAB + i * 8, Ah + src);
                cpasync8(sb + OFF_AL + r * LDAB + i * 8, Al + src);
            }
        }
        for (int e = t; e < BN * 8; e += 256) {
            int n = e >> 3, i = e & 7;
            size_t src = (size_t)(bn + n) * K + k0 + i * 8;
            cpasync16(sb + OFF_BH + n * LDAB + i * 16, BhT + src);
            cpasync16(sb + OFF_BL + n * LDAB + i * 16, BlT + src);
        }
    };

    float acc[MT][4][4];
#pragma unroll
    for (int i = 0; i < MT; i++)
#pragma unroll
        for (int j = 0; j < 4; j++)
#pragma unroll
            for (int q = 0; q < 4; q++) acc[i][j][q] = 0.f;

    constexpr int NCH = K / 64;
    stage(0, 0);
    CP_COMMIT();

    for (int ch = 0; ch < NCH; ch++) {
        if (ch + 1 < NCH) {
            stage(ch + 1, (ch + 1) & 1);
            CP_COMMIT();
            CP_WAIT1();
        } else {
            CP_WAIT0();
        }
        __syncthreads();

        const uint32_t sb = sbase + (uint32_t)(ch & 1) * BUF_BYTES;
        const uint32_t aH = sb + OFF_AH + aoffL;
        const uint32_t aL = sb + OFF_AL + aoffL;
        const uint32_t bH = sb + OFF_BH + boffL;
        const uint32_t bL = sb + OFF_BL + boffL;

#pragma unroll
        for (int ks = 0; ks < 4; ks++) {
            uint32_t ah[MT][4], al[MT][4], bh[4][2], bl[4][2];
#pragma unroll
            for (int mt = 0; mt < MT; mt++) {
                ldsm_x4(ah[mt], aH + mt * 16 * LDAB + ks * 32);
                ldsm_x4(al[mt], aL + mt * 16 * LDAB + ks * 32);
            }
#pragma unroll
            for (int nt = 0; nt < 4; nt++) {
                ldsm_x2(bh[nt], bH + nt * 8 * LDAB + ks * 32);
                ldsm_x2(bl[nt], bL + nt * 8 * LDAB + ks * 32);
            }
#pragma unroll
            for (int mt = 0; mt < MT; mt++)
#pragma unroll
                for (int nt = 0; nt < 4; nt++) {
                    mma16816(acc[mt][nt], ah[mt], bh[nt]);
                    mma16816(acc[mt][nt], ah[mt], bl[nt]);
                    mma16816(acc[mt][nt], al[mt], bh[nt]);
                }
        }
        __syncthreads();
    }

#pragma unroll
    for (int mt = 0; mt < MT; mt++) {
#pragma unroll
        for (int nt = 0; nt < 4; nt++) {
            int col = bn + wn * 32 + nt * 8 + tc * 2;
            float b0 = __ldg(&bias[col]);
            float b1 = __ldg(&bias[col + 1]);
            int r0 = bm + wm * (128 / WM) + mt * 16 + g;
            float v00 = fmaxf(acc[mt][nt][0] + b0, 0.f);
            float v01 = fmaxf(acc[mt][nt][1] + b1, 0.f);
            float v10 = fmaxf(acc[mt][nt][2] + b0, 0.f);
            float v11 = fmaxf(acc[mt][nt][3] + b1, 0.f);
            if (OUTBF) {
                float h00 = __bfloat162float(__float2bfloat16(v00));
                float h01 = __bfloat162float(__float2bfloat16(v01));
                float h10 = __bfloat162float(__float2bfloat16(v10));
                float h11 = __bfloat162float(__float2bfloat16(v11));
                *(uint32_t*)&outh[(size_t)r0 * NTOT + col]       = bf2w(v00, v01);
                *(uint32_t*)&outl[(size_t)r0 * NTOT + col]       = bf2w(v00 - h00, v01 - h01);
                *(uint32_t*)&outh[(size_t)(r0 + 8) * NTOT + col] = bf2w(v10, v11);
                *(uint32_t*)&outl[(size_t)(r0 + 8) * NTOT + col] = bf2w(v10 - h10, v11 - h11);
            } else {
                float2 v0 = {v00, v01}, v1 = {v10, v11};
                *(float2*)&outf[(size_t)r0 * NTOT + col]       = v0;
                *(float2*)&outf[(size_t)(r0 + 8) * NTOT + col] = v1;
            }
        }
    }
}

// conv1: BN=32, WM=8, GRAN=8
__global__ void __launch_bounds__(256) conv1m_kernel(const float* __restrict__ bias) {
    mgemm_body<32, 8, 32, 192, 1, 400, 20, 4, 84, 3, 8, 8, 1>(
        g_imgh, g_imgl, g_W1T_h, g_W1T_l, bias, g_c1h, g_c1l, nullptr);
}
__global__ void __launch_bounds__(256) conv2m_kernel(const float* __restrict__ bias) {
    mgemm_body<64, 4, 64, 512, 1, 81, 9, 2, 20, 32, 4, 16, 1>(
        g_c1h, g_c1l, g_W2T_h, g_W2T_l, bias, g_c2h, g_c2l, nullptr);
}
__global__ void __launch_bounds__(256) conv3m_kernel(const float* __restrict__ bias) {
    mgemm_body<64, 4, 64, 576, 1, 49, 7, 1, 9, 64, 3, 16, 1>(
        g_c2h, g_c2l, g_W3T_h, g_W3T_l, bias, g_c3h, g_c3l, nullptr);
}
__global__ void __launch_bounds__(256) fcm_kernel(const float* __restrict__ bias) {
    mgemm_body<64, 4, 512, 3136, 0, 1, 1, 1, 1, 1, 1, 16, 0>(
        g_c3h, g_c3l, g_WfcT_h, g_WfcT_l, bias, nullptr, nullptr, g_feat);
}

// ---------------- xw: SGEMM 64x64x16 f32x2 (EPI: biases + one-hot) --------
__device__ __forceinline__ void xw_body(
    const float* __restrict__ A, const float* __restrict__ B,
    float* __restrict__ C, int N, int K, int ldb,
    const float* __restrict__ bias1, const float* __restrict__ bias2,
    const float* __restrict__ WihFull, const int* __restrict__ pos)
{
    __shared__ __align__(16) float As[16][68];
    __shared__ __align__(16) float Bs[16][68];
    int bm = blockIdx.y * 64, bn = blockIdx.x * 64;
    int t = threadIdx.x;
    int tm = t >> 4, tn = t & 15;

    unsigned long long acc2[2][4];
#pragma unroll
    for (int i = 0; i < 2; i++)
#pragma unroll
        for (int j = 0; j < 4; j++) acc2[i][j] = 0ull;

    int ar = t >> 2, ac = (t & 3) * 4;

    float4 avR, bvR;
    auto load_tile = [&](int k0) {
        avR = *(const float4*)(A + (size_t)(bm + ar) * K + k0 + ac);
        bvR = *(const float4*)(B + (size_t)(bn + ar) * ldb + k0 + ac);
    };
    auto store_tile = [&]() {
        As[ac + 0][ar] = avR.x; As[ac + 1][ar] = avR.y;
        As[ac + 2][ar] = avR.z; As[ac + 3][ar] = avR.w;
        Bs[ac + 0][ar] = bvR.x; Bs[ac + 1][ar] = bvR.y;
        Bs[ac + 2][ar] = bvR.z; Bs[ac + 3][ar] = bvR.w;
    };

    const int NIT = K / 16;
    load_tile(0);
    store_tile();
    __syncthreads();

    for (int it = 1; it <= NIT; it++) {
        if (it < NIT) load_tile(it * 16);
#pragma unroll
        for (int kk = 0; kk < 16; kk++) {
            const unsigned long long* ap =
                reinterpret_cast<const unsigned long long*>(&As[kk][tm * 4]);
            unsigned long long a2[2] = {ap[0], ap[1]};
            float4 bq = *(const float4*)&Bs[kk][tn * 4];
            unsigned long long b2[4] = {pack2(bq.x, bq.x), pack2(bq.y, bq.y),
                                        pack2(bq.z, bq.z), pack2(bq.w, bq.w)};
#pragma unroll
            for (int i = 0; i < 2; i++)
#pragma unroll
                for (int j = 0; j < 4; j++)
                    fma2(acc2[i][j], a2[i], b2[j]);
        }
        if (it < NIT) {
            __syncthreads();
            store_tile();
            __syncthreads();
        }
    }
#pragma unroll
    for (int i2 = 0; i2 < 2; i2++) {
        float2 u[4];
#pragma unroll
        for (int j = 0; j < 4; j++) u[j] = unpack2(acc2[i2][j]);
#pragma unroll
        for (int half = 0; half < 2; half++) {
            int row = bm + tm * 4 + 2 * i2 + half;
            int p0 = pos[2 * row], p1 = pos[2 * row + 1];
#pragma unroll
            for (int j = 0; j < 4; j++) {
                int col = bn + tn * 4 + j;
                float v = half ? u[j].y : u[j].x;
                v += bias1[col] + bias2[col]
                   + WihFull[(size_t)col * 532 + 512 + p0]
                   + WihFull[(size_t)col * 532 + 522 + p1];
                C[(size_t)row * N + col] = v;
            }
        }
    }
}

__global__ void __launch_bounds__(256) xw_kernel(
    const float* __restrict__ Wih, const float* __restrict__ bih,
    const float* __restrict__ bhh, const int* __restrict__ pos)
{
    xw_body(g_feat, Wih, g_xw, 512, 512, 532, bih, bhh, Wih, pos);
}

// ---------------- persistent LSTM: 32 blocks x 128 threads --------------
// Sync rebuilt: NO threadfence. Every thread release-arrives on its CTA's
// flag (ordering its own h stores); threads t<32 acquire-poll the 32 flags.
__device__ __forceinline__ float sigmoidf_(float x) {
    return 1.0f / (1.0f + __expf(-x));
}

__global__ void __launch_bounds__(128) lstm_kernel(
    const int* __restrict__ done, const float* __restrict__ h0,
    const float* __restrict__ c0, const float* __restrict__ Whh,
    float* __restrict__ out)
{
    int k = blockIdx.x;
    int t = threadIdx.x;
    int lane = t & 31, w = t >> 5;

    __shared__ float whh_s[16][HID];
    __shared__ float h_sh[HID][BBATCH];
    __shared__ float c_s[4][BBATCH];
    __shared__ float gate_s[4][4][BBATCH];
    __shared__ float m_all[TSTEPS][BBATCH];   // all masks preloaded

    for (int idx = t; idx < 16 * HID; idx += 128) {
        int r = idx >> 7, j = idx & 127;
        int G = (r >> 2) * HID + k * 4 + (r & 3);
        whh_s[r][j] = Whh[(size_t)G * HID + j];
    }
    for (int idx = t; idx < TSTEPS * BBATCH; idx += 128)
        m_all[idx >> 5][idx & 31] = 1.0f - (float)done[idx];
    c_s[w][lane] = c0[lane * HID + k * 4 + w];
    __stcg(&g_hT[0][(k * 4 + w) * BBATCH + lane], h0[lane * HID + k * 4 + w]);

    unsigned nbar = 1;
    // barrier: every thread release-arrives; t<32 acquire-polls all CTAs
    {
        red_rel(&g_wf[k * 32]);
        if (t < 32) { while (ld_acq(&g_wf[t * 32]) < 128u * nbar) {} }
        __syncthreads();
    }

    float h_last = 0.f;
    for (int step = 0; step < TSTEPS; step++) {
        int p = step & 1;
        for (int idx = t; idx < HID * BBATCH; idx += 128) {
            h_sh[idx >> 5][idx & 31] = __ldcg(&g_hT[p][idx]) * m_all[step][idx & 31];
        }
        __syncthreads();

        // gates: thread (gate=w, batch=lane) accumulates 4 units
        float acc[4];
        const float* xwr = g_xw + (size_t)(step * BBATCH + lane) * 512 + w * HID + k * 4;
#pragma unroll
        for (int ul = 0; ul < 4; ul++) acc[ul] = xwr[ul];
#pragma unroll 4
        for (int j = 0; j < HID; j++) {
            float hv = h_sh[j][lane];
#pragma unroll
            for (int ul = 0; ul < 4; ul++) acc[ul] += hv * whh_s[w * 4 + ul][j];
        }
#pragma unroll
        for (int ul = 0; ul < 4; ul++) gate_s[w][ul][lane] = acc[ul];
        __syncthreads();

        // update: thread (unit=w, batch=lane)
        float iv = sigmoidf_(gate_s[0][w][lane]);
        float fv = sigmoidf_(gate_s[1][w][lane]);
        float gv = tanhf(gate_s[2][w][lane]);
        float ov = sigmoidf_(gate_s[3][w][lane]);
        float cc = fv * (c_s[w][lane] * m_all[step][lane]) + iv * gv;
        c_s[w][lane] = cc;
        float hh = ov * tanhf(cc);
        h_last = hh;
        __stcg(&g_hT[1 - p][(k * 4 + w) * BBATCH + lane], hh);
        g_hs[(size_t)(step * BBATCH + lane) * HID + k * 4 + w] = hh;

        if (step + 1 < TSTEPS) {
            nbar++;
            red_rel(&g_wf[k * 32]);
            if (t < 32) { while (ld_acq(&g_wf[t * 32]) < 128u * nbar) {} }
            __syncthreads();
        }
    }
    // final h, c -> out (B,1,128) regions
    out[12288 + lane * HID + k * 4 + w] = h_last;
    out[16384 + lane * HID + k * 4 + w] = c_s[w][lane];
}

// ---------------- heads: logits (2048x5) + value (2048x1) ---------------
__global__ void heads_kernel(
    const float* __restrict__ Wp, const float* __restrict__ bp,
    const float* __restrict__ Wv, const float* __restrict__ bv,
    float* __restrict__ out)
{
    int row = blockIdx.x * 8 + threadIdx.y;
    int lane = threadIdx.x;
    const float* h = g_hs + (size_t)row * HID;
    float4 hv = *(const float4*)&h[lane * 4];
    float vals[4] = {hv.x, hv.y, hv.z, hv.w};
    float r[6];
#pragma unroll
    for (int a = 0; a < 5; a++) {
        float s = 0.f;
#pragma unroll
        for (int q = 0; q < 4; q++) s += vals[q] * __ldg(&Wp[(lane * 4 + q) * 5 + a]);
        r[a] = s;
    }
    {
        float s = 0.f;
#pragma unroll
        for (int q = 0; q < 4; q++) s += vals[q] * __ldg(&Wv[lane * 4 + q]);
        r[5] = s;
    }
#pragma unroll
    for (int a = 0; a < 6; a++)
#pragma unroll
        for (int off = 16; off > 0; off >>= 1)
            r[a] += __shfl_xor_sync(0xffffffffu, r[a], off);
    if (lane == 0) {
#pragma unroll
        for (int a = 0; a < 5; a++) out[(size_t)row * 5 + a] = r[a] + __ldg(&bp[a]);
        out[10240 + row] = r[5] + __ldg(&bv[0]);
    }
}

// ---------------- launch ----------------
extern "C" void kernel_launch(void* const* d_in, const int* in_sizes, int n_in,
                              void* d_out, int out_size)
{
    const float* image    = (const float*)d_in[0];
    const int*   position = (const int*)d_in[1];
    const int*   done     = (const int*)d_in[2];
    const float* h0       = (const float*)d_in[3];
    const float* c0       = (const float*)d_in[4];
    const float* W1  = (const float*)d_in[5];
    const float* b1  = (const float*)d_in[6];
    const float* W2  = (const float*)d_in[7];
    const float* b2  = (const float*)d_in[8];
    const float* W3  = (const float*)d_in[9];
    const float* b3  = (const float*)d_in[10];
    const float* Wfc = (const float*)d_in[11];
    const float* bfc = (const float*)d_in[12];
    const float* Wih = (const float*)d_in[13];
    const float* Whh = (const float*)d_in[14];
    const float* bih = (const float*)d_in[15];
    const float* bhh = (const float*)d_in[16];
    const float* Wp  = (const float*)d_in[17];
    const float* bp  = (const float*)d_in[18];
    const float* Wv  = (const float*)d_in[19];
    const float* bv  = (const float*)d_in[20];
    float* out = (float*)d_out;

    const int SM_C1 = 2 * (2 * 128 * 144 + 2 * 32 * 144) + 192 * 4 + 512;
    const int SM_C2 = 110592 + 512 * 4 + 512;
    const int SM_C3 = 110592 + 576 * 4 + 512;
    const int SM_FC = 110592;
    cudaFuncSetAttribute(conv1m_kernel, cudaFuncAttributeMaxDynamicSharedMemorySize, SM_C1);
    cudaFuncSetAttribute(conv2m_kernel, cudaFuncAttributeMaxDynamicSharedMemorySize, SM_C2);
    cudaFuncSetAttribute(conv3m_kernel, cudaFuncAttributeMaxDynamicSharedMemorySize, SM_C3);
    cudaFuncSetAttribute(fcm_kernel,   cudaFuncAttributeMaxDynamicSharedMemorySize, SM_FC);

    init_kernel<<<1, 32>>>();
    imgsplit_kernel<<<2048, 256>>>(image);
    wsplit_c1_kernel<<<8, 256>>>(W1);
    conv1m_kernel<<<dim3(1, 819200 / 128), 256, SM_C1>>>(b1);
    wsplit_c2_kernel<<<32, 256>>>(W2);
    conv2m_kernel<<<dim3(1, 165888 / 128), 256, SM_C2>>>(b2);
    wsplit_c3_kernel<<<32, 256>>>(W3);
    conv3m_kernel<<<dim3(1, 100352 / 128), 256, SM_C3>>>(b3);
    wsplit_fc_kernel<<<512, 256>>>(Wfc);
    fcm_kernel<<<dim3(8, 2048 / 128), 256, SM_FC>>>(bfc);
    xw_kernel<<<dim3(8, 32), 256>>>(Wih, bih, bhh, position);
    lstm_kernel<<<32, 128>>>(done, h0, c0, Whh, out);
    heads_kernel<<<256, dim3(32, 8)>>>(Wp, bp, Wv, bv, out);
}

// round 17
// speedup vs baseline: 2.2558x; 1.4217x over previous
#include <cuda_runtime.h>
#include <cuda_bf16.h>
#include <cstdint>

// ---------------- problem constants ----------------
#define NIMG 2048          // T*B
#define TSTEPS 64
#define BBATCH 32
#define HID 128

// ---------------- device scratch -------------------
__device__ __nv_bfloat16 g_imgh[NIMG * 21168 + 64];
__device__ __nv_bfloat16 g_imgl[NIMG * 21168 + 64];
__device__ __nv_bfloat16 g_c1h[NIMG * 400 * 32];
__device__ __nv_bfloat16 g_c1l[NIMG * 400 * 32];
__device__ __nv_bfloat16 g_c2h[NIMG * 81 * 64];
__device__ __nv_bfloat16 g_c2l[NIMG * 81 * 64];
__device__ __nv_bfloat16 g_c3h[NIMG * 3136];
__device__ __nv_bfloat16 g_c3l[NIMG * 3136];
__device__ float g_feat[NIMG * 512];
__device__ float g_xw[NIMG * 512];
__device__ float g_hs[NIMG * HID];

__device__ __nv_bfloat16 g_WfcT_h[512 * 3136];
__device__ __nv_bfloat16 g_WfcT_l[512 * 3136];
__device__ __nv_bfloat16 g_W1T_h[32 * 192];
__device__ __nv_bfloat16 g_W1T_l[32 * 192];
__device__ __nv_bfloat16 g_W2T_h[64 * 512];
__device__ __nv_bfloat16 g_W2T_l[64 * 512];
__device__ __nv_bfloat16 g_W3T_h[64 * 576];
__device__ __nv_bfloat16 g_W3T_l[64 * 576];

// ---------------- packed f32x2 helpers (xw kernel) ----------------
__device__ __forceinline__ void fma2(unsigned long long& d,
                                     unsigned long long a,
                                     unsigned long long b) {
    asm("fma.rn.f32x2 %0, %1, %2, %3;" : "=l"(d) : "l"(a), "l"(b), "l"(d));
}
__device__ __forceinline__ unsigned long long pack2(float lo, float hi) {
    unsigned long long r;
    asm("mov.b64 %0, {%1, %2};" : "=l"(r) : "f"(lo), "f"(hi));
    return r;
}
__device__ __forceinline__ float2 unpack2(unsigned long long v) {
    float2 r;
    asm("mov.b64 {%0, %1}, %2;" : "=f"(r.x), "=f"(r.y) : "l"(v));
    return r;
}
__device__ __forceinline__ uint32_t bf2w(float a, float b) {
    __nv_bfloat162 p = __floats2bfloat162_rn(a, b);
    return *reinterpret_cast<uint32_t*>(&p);
}

// ---------------- warp MMA + async-copy + cluster helpers ------------------
__device__ __forceinline__ uint32_t smem_u32(const void* p) {
    uint32_t a;
    asm("{ .reg .u64 t; cvta.to.shared.u64 t, %1; cvt.u32.u64 %0, t; }"
        : "=r"(a) : "l"(p));
    return a;
}
__device__ __forceinline__ void mma16816(float* c, const uint32_t* a, const uint32_t* b) {
    asm volatile(
        "mma.sync.aligned.m16n8k16.row.col.f32.bf16.bf16.f32 "
        "{%0,%1,%2,%3}, {%4,%5,%6,%7}, {%8,%9}, {%0,%1,%2,%3};"
        : "+f"(c[0]), "+f"(c[1]), "+f"(c[2]), "+f"(c[3])
        : "r"(a[0]), "r"(a[1]), "r"(a[2]), "r"(a[3]), "r"(b[0]), "r"(b[1]));
}
__device__ __forceinline__ void ldsm_x4(uint32_t* r, uint32_t addr) {
    asm volatile("ldmatrix.sync.aligned.m8n8.x4.shared.b16 {%0,%1,%2,%3}, [%4];"
                 : "=r"(r[0]), "=r"(r[1]), "=r"(r[2]), "=r"(r[3]) : "r"(addr));
}
__device__ __forceinline__ void ldsm_x2(uint32_t* r, uint32_t addr) {
    asm volatile("ldmatrix.sync.aligned.m8n8.x2.shared.b16 {%0,%1}, [%2];"
                 : "=r"(r[0]), "=r"(r[1]) : "r"(addr));
}
__device__ __forceinline__ void cpasync16(uint32_t dst, const void* src) {
    asm volatile("cp.async.cg.shared.global [%0], [%1], 16;"
                 :: "r"(dst), "l"(src) : "memory");
}
__device__ __forceinline__ void cpasync8(uint32_t dst, const void* src) {
    asm volatile("cp.async.ca.shared.global [%0], [%1], 8;"
                 :: "r"(dst), "l"(src) : "memory");
}
#define CP_COMMIT() asm volatile("cp.async.commit_group;" ::: "memory")
#define CP_WAIT1()  asm volatile("cp.async.wait_group 1;" ::: "memory")
#define CP_WAIT0()  asm volatile("cp.async.wait_group 0;" ::: "memory")

__device__ __forceinline__ uint32_t mapa_addr(uint32_t a, int r) {
    uint32_t d;
    asm("mapa.shared::cluster.u32 %0, %1, %2;" : "=r"(d) : "r"(a), "r"(r));
    return d;
}
__device__ __forceinline__ void st_cluster(uint32_t a, float v) {
    asm volatile("st.shared::cluster.f32 [%0], %1;" :: "r"(a), "f"(v) : "memory");
}
#define CLUSTER_SYNC() do { \
    asm volatile("barrier.cluster.arrive.aligned;" ::: "memory"); \
    asm volatile("barrier.cluster.wait.aligned;"   ::: "memory"); \
} while (0)

__global__ void init_kernel() {}   // no-op (kept for launch-order stability)

// ---------------- image fp32 -> bf16 hi/lo split ----------------
__global__ void imgsplit_kernel(const float* __restrict__ img) {
    const int total4 = NIMG * 21168 / 4;
    for (int i = blockIdx.x * blockDim.x + threadIdx.x; i < total4;
         i += gridDim.x * blockDim.x) {
        float4 v = *(const float4*)(img + (size_t)i * 4);
        float h0 = __bfloat162float(__float2bfloat16(v.x));
        float h1 = __bfloat162float(__float2bfloat16(v.y));
        float h2 = __bfloat162float(__float2bfloat16(v.z));
        float h3 = __bfloat162float(__float2bfloat16(v.w));
        uint2 wh = {bf2w(v.x, v.y), bf2w(v.z, v.w)};
        uint2 wl = {bf2w(v.x - h0, v.y - h1), bf2w(v.z - h2, v.w - h3)};
        *(uint2*)(g_imgh + (size_t)i * 4) = wh;
        *(uint2*)(g_imgl + (size_t)i * 4) = wl;
    }
}

// ---------------- weight pre-transpose + bf16 hi/lo split -----------------
template<int K, int N>
__device__ __forceinline__ void wsplit_body(const float* __restrict__ W,
                                            __nv_bfloat16* __restrict__ Th,
                                            __nv_bfloat16* __restrict__ Tl) {
    int total = K * N;
    for (int idx = blockIdx.x * blockDim.x + threadIdx.x; idx < total;
         idx += gridDim.x * blockDim.x) {
        int n = idx / K, k = idx - n * K;
        float x = __ldg(&W[(size_t)k * N + n]);
        __nv_bfloat16 h = __float2bfloat16(x);
        float r = x - __bfloat162float(h);
        Th[idx] = h;
        Tl[idx] = __float2bfloat16(r);
    }
}
__global__ void wsplit_fc_kernel(const float* __restrict__ W) {
    wsplit_body<3136, 512>(W, g_WfcT_h, g_WfcT_l);
}
__global__ void wsplit_c1_kernel(const float* __restrict__ W) {
    wsplit_body<192, 32>(W, g_W1T_h, g_W1T_l);
}
__global__ void wsplit_c2_kernel(const float* __restrict__ W) {
    wsplit_body<512, 64>(W, g_W2T_h, g_W2T_l);
}
__global__ void wsplit_c3_kernel(const float* __restrict__ W) {
    wsplit_body<576, 64>(W, g_W3T_h, g_W3T_l);
}

// ============ HMMA bf16x3 GEMM, cp.async double-buffered ============
template<int BN, int WM, int NTOT, int K, int IM2COL, int P, int PW, int S,
         int IW, int CI, int KW, int GRAN, int OUTBF>
__device__ void mgemm_body(const __nv_bfloat16* __restrict__ Ah,
                           const __nv_bfloat16* __restrict__ Al,
                           const __nv_bfloat16* __restrict__ BhT,
                           const __nv_bfloat16* __restrict__ BlT,
                           const float* __restrict__ bias,
                           __nv_bfloat16* __restrict__ outh,
                           __nv_bfloat16* __restrict__ outl,
                           float* __restrict__ outf)
{
    extern __shared__ char smem[];
    constexpr int WN  = 8 / WM;
    constexpr int MT  = 128 / (WM * 16);
    constexpr int LDAB = 144;
    constexpr int A_BYTES = 128 * LDAB;
    constexpr int B_BYTES = BN * LDAB;
    constexpr int BUF_BYTES = 2 * A_BYTES + 2 * B_BYTES;
    constexpr int OFF_AH  = 0;
    constexpr int OFF_AL  = A_BYTES;
    constexpr int OFF_BH  = 2 * A_BYTES;
    constexpr int OFF_BL  = 2 * A_BYTES + B_BYTES;
    constexpr int OFF_KO  = 2 * BUF_BYTES;
    constexpr int OFF_ROW = OFF_KO + (IM2COL ? K * 4 : 0);

    const int t = threadIdx.x;
    const int wid = t >> 5, L = t & 31;
    const int wm = wid / WN, wn = wid % WN;
    const int g = L >> 2, tc = L & 3;
    const int bm = blockIdx.y * 128;
    const int bn = blockIdx.x * BN;
    uint32_t sbase = smem_u32(smem);
    int* s_koff = (int*)(smem + OFF_KO);
    int* s_row  = (int*)(smem + OFF_ROW);

    if (IM2COL) {
        for (int i = t; i < K; i += 256) {
            int ky = i / (KW * CI);
            int r  = i - ky * (KW * CI);
            int kx = r / CI;
            int ci = r - kx * CI;
            s_koff[i] = (ky * IW + kx) * CI + ci;
        }
        if (t < 128) {
            int m = bm + t;
            int n = m / P;
            int p = m - n * P;
            int py = p / PW;
            int px = p - py * PW;
            s_row[t] = n * (IW * IW * CI) + (py * S * IW + px * S) * CI;
        }
        __syncthreads();
    }

    const uint32_t aoffL = (uint32_t)((wm * (128 / WM) + (L & 15)) * LDAB + (L >> 4) * 16);
    const uint32_t boffL = (uint32_t)((wn * 32 + (L & 7)) * LDAB + ((L >> 3) & 1) * 16);

    constexpr int UPS = (IM2COL && CI == 32) ? 4 : 8;

    auto stage = [&](int ch, int buf) {
        const int k0 = ch * 64;
        const uint32_t sb = sbase + buf * BUF_BYTES;
        if (GRAN == 16) {
            for (int u = t; u < 1024; u += 256) {
                int r = u >> 3, i = u & 7;
                int seg = i / UPS, isg = i - seg * UPS;
                size_t src;
                if (IM2COL) src = (size_t)s_row[r] + s_koff[k0 + seg * CI] + isg * 8;
                else        src = (size_t)(bm + r) * K + k0 + i * 8;
                cpasync16(sb + OFF_AH + r * LDAB + i * 16, Ah + src);
                cpasync16(sb + OFF_AL + r * LDAB + i * 16, Al + src);
            }
        } else {
            for (int u = t; u < 2048; u += 256) {
                int r = u >> 4, i = u & 15;
                size_t src = (size_t)s_row[r] + s_koff[k0 + i * 4];
                cpasync8(sb + OFF_AH + r * LDAB + i * 8, Ah + src);
                cpasync8(sb + OFF_AL + r * LDAB + i * 8, Al + src);
            }
        }
        for (int e = t; e < BN * 8; e += 256) {
            int n = e >> 3, i = e & 7;
            size_t src = (size_t)(bn + n) * K + k0 + i * 8;
            cpasync16(sb + OFF_BH + n * LDAB + i * 16, BhT + src);
            cpasync16(sb + OFF_BL + n * LDAB + i * 16, BlT + src);
        }
    };

    float acc[MT][4][4];
#pragma unroll
    for (int i = 0; i < MT; i++)
#pragma unroll
        for (int j = 0; j < 4; j++)
#pragma unroll
            for (int q = 0; q < 4; q++) acc[i][j][q] = 0.f;

    constexpr int NCH = K / 64;
    stage(0, 0);
    CP_COMMIT();

    for (int ch = 0; ch < NCH; ch++) {
        if (ch + 1 < NCH) {
            stage(ch + 1, (ch + 1) & 1);
            CP_COMMIT();
            CP_WAIT1();
        } else {
            CP_WAIT0();
        }
        __syncthreads();

        const uint32_t sb = sbase + (uint32_t)(ch & 1) * BUF_BYTES;
        const uint32_t aH = sb + OFF_AH + aoffL;
        const uint32_t aL = sb + OFF_AL + aoffL;
        const uint32_t bH = sb + OFF_BH + boffL;
        const uint32_t bL = sb + OFF_BL + boffL;

#pragma unroll
        for (int ks = 0; ks < 4; ks++) {
            uint32_t ah[MT][4], al[MT][4], bh[4][2], bl[4][2];
#pragma unroll
            for (int mt = 0; mt < MT; mt++) {
                ldsm_x4(ah[mt], aH + mt * 16 * LDAB + ks * 32);
                ldsm_x4(al[mt], aL + mt * 16 * LDAB + ks * 32);
            }
#pragma unroll
            for (int nt = 0; nt < 4; nt++) {
                ldsm_x2(bh[nt], bH + nt * 8 * LDAB + ks * 32);
                ldsm_x2(bl[nt], bL + nt * 8 * LDAB + ks * 32);
            }
#pragma unroll
            for (int mt = 0; mt < MT; mt++)
#pragma unroll
                for (int nt = 0; nt < 4; nt++) {
                    mma16816(acc[mt][nt], ah[mt], bh[nt]);
                    mma16816(acc[mt][nt], ah[mt], bl[nt]);
                    mma16816(acc[mt][nt], al[mt], bh[nt]);
                }
        }
        __syncthreads();
    }

#pragma unroll
    for (int mt = 0; mt < MT; mt++) {
#pragma unroll
        for (int nt = 0; nt < 4; nt++) {
            int col = bn + wn * 32 + nt * 8 + tc * 2;
            float b0 = __ldg(&bias[col]);
            float b1 = __ldg(&bias[col + 1]);
            int r0 = bm + wm * (128 / WM) + mt * 16 + g;
            float v00 = fmaxf(acc[mt][nt][0] + b0, 0.f);
            float v01 = fmaxf(acc[mt][nt][1] + b1, 0.f);
            float v10 = fmaxf(acc[mt][nt][2] + b0, 0.f);
            float v11 = fmaxf(acc[mt][nt][3] + b1, 0.f);
            if (OUTBF) {
                float h00 = __bfloat162float(__float2bfloat16(v00));
                float h01 = __bfloat162float(__float2bfloat16(v01));
                float h10 = __bfloat162float(__float2bfloat16(v10));
                float h11 = __bfloat162float(__float2bfloat16(v11));
                *(uint32_t*)&outh[(size_t)r0 * NTOT + col]       = bf2w(v00, v01);
                *(uint32_t*)&outl[(size_t)r0 * NTOT + col]       = bf2w(v00 - h00, v01 - h01);
                *(uint32_t*)&outh[(size_t)(r0 + 8) * NTOT + col] = bf2w(v10, v11);
                *(uint32_t*)&outl[(size_t)(r0 + 8) * NTOT + col] = bf2w(v10 - h10, v11 - h11);
            } else {
                float2 v0 = {v00, v01}, v1 = {v10, v11};
                *(float2*)&outf[(size_t)r0 * NTOT + col]       = v0;
                *(float2*)&outf[(size_t)(r0 + 8) * NTOT + col] = v1;
            }
        }
    }
}

__global__ void __launch_bounds__(256) conv1m_kernel(const float* __restrict__ bias) {
    mgemm_body<32, 8, 32, 192, 1, 400, 20, 4, 84, 3, 8, 8, 1>(
        g_imgh, g_imgl, g_W1T_h, g_W1T_l, bias, g_c1h, g_c1l, nullptr);
}
__global__ void __launch_bounds__(256) conv2m_kernel(const float* __restrict__ bias) {
    mgemm_body<64, 4, 64, 512, 1, 81, 9, 2, 20, 32, 4, 16, 1>(
        g_c1h, g_c1l, g_W2T_h, g_W2T_l, bias, g_c2h, g_c2l, nullptr);
}
__global__ void __launch_bounds__(256) conv3m_kernel(const float* __restrict__ bias) {
    mgemm_body<64, 4, 64, 576, 1, 49, 7, 1, 9, 64, 3, 16, 1>(
        g_c2h, g_c2l, g_W3T_h, g_W3T_l, bias, g_c3h, g_c3l, nullptr);
}
__global__ void __launch_bounds__(256) fcm_kernel(const float* __restrict__ bias) {
    mgemm_body<64, 4, 512, 3136, 0, 1, 1, 1, 1, 1, 1, 16, 0>(
        g_c3h, g_c3l, g_WfcT_h, g_WfcT_l, bias, nullptr, nullptr, g_feat);
}

// ---------------- xw: SGEMM 64x64x16 f32x2 (EPI: biases + one-hot) --------
__device__ __forceinline__ void xw_body(
    const float* __restrict__ A, const float* __restrict__ B,
    float* __restrict__ C, int N, int K, int ldb,
    const float* __restrict__ bias1, const float* __restrict__ bias2,
    const float* __restrict__ WihFull, const int* __restrict__ pos)
{
    __shared__ __align__(16) float As[16][68];
    __shared__ __align__(16) float Bs[16][68];
    int bm = blockIdx.y * 64, bn = blockIdx.x * 64;
    int t = threadIdx.x;
    int tm = t >> 4, tn = t & 15;

    unsigned long long acc2[2][4];
#pragma unroll
    for (int i = 0; i < 2; i++)
#pragma unroll
        for (int j = 0; j < 4; j++) acc2[i][j] = 0ull;

    int ar = t >> 2, ac = (t & 3) * 4;

    float4 avR, bvR;
    auto load_tile = [&](int k0) {
        avR = *(const float4*)(A + (size_t)(bm + ar) * K + k0 + ac);
        bvR = *(const float4*)(B + (size_t)(bn + ar) * ldb + k0 + ac);
    };
    auto store_tile = [&]() {
        As[ac + 0][ar] = avR.x; As[ac + 1][ar] = avR.y;
        As[ac + 2][ar] = avR.z; As[ac + 3][ar] = avR.w;
        Bs[ac + 0][ar] = bvR.x; Bs[ac + 1][ar] = bvR.y;
        Bs[ac + 2][ar] = bvR.z; Bs[ac + 3][ar] = bvR.w;
    };

    const int NIT = K / 16;
    load_tile(0);
    store_tile();
    __syncthreads();

    for (int it = 1; it <= NIT; it++) {
        if (it < NIT) load_tile(it * 16);
#pragma unroll
        for (int kk = 0; kk < 16; kk++) {
            const unsigned long long* ap =
                reinterpret_cast<const unsigned long long*>(&As[kk][tm * 4]);
            unsigned long long a2[2] = {ap[0], ap[1]};
            float4 bq = *(const float4*)&Bs[kk][tn * 4];
            unsigned long long b2[4] = {pack2(bq.x, bq.x), pack2(bq.y, bq.y),
                                        pack2(bq.z, bq.z), pack2(bq.w, bq.w)};
#pragma unroll
            for (int i = 0; i < 2; i++)
#pragma unroll
                for (int j = 0; j < 4; j++)
                    fma2(acc2[i][j], a2[i], b2[j]);
        }
        if (it < NIT) {
            __syncthreads();
            store_tile();
            __syncthreads();
        }
    }
#pragma unroll
    for (int i2 = 0; i2 < 2; i2++) {
        float2 u[4];
#pragma unroll
        for (int j = 0; j < 4; j++) u[j] = unpack2(acc2[i2][j]);
#pragma unroll
        for (int half = 0; half < 2; half++) {
            int row = bm + tm * 4 + 2 * i2 + half;
            int p0 = pos[2 * row], p1 = pos[2 * row + 1];
#pragma unroll
            for (int j = 0; j < 4; j++) {
                int col = bn + tn * 4 + j;
                float v = half ? u[j].y : u[j].x;
                v += bias1[col] + bias2[col]
                   + WihFull[(size_t)col * 532 + 512 + p0]
                   + WihFull[(size_t)col * 532 + 522 + p1];
                C[(size_t)row * N + col] = v;
            }
        }
    }
}

__global__ void __launch_bounds__(256) xw_kernel(
    const float* __restrict__ Wih, const float* __restrict__ bih,
    const float* __restrict__ bhh, const int* __restrict__ pos)
{
    xw_body(g_feat, Wih, g_xw, 512, 512, 532, bih, bhh, Wih, pos);
}

// ---------------- LSTM: batch-parallel, cluster(4) per batch element ------
// 32 clusters x 4 CTAs x 128 threads. CTA owns 32 hidden units of ONE batch.
// Thread = one gate-row (dot over 128 h). h exchanged via DSMEM; only
// intra-cluster barriers — zero global sync in the recurrence.
__device__ __forceinline__ float sigmoidf_(float x) {
    return 1.0f / (1.0f + __expf(-x));
}

__global__ void __launch_bounds__(128) __cluster_dims__(4, 1, 1)
lstm_kernel(const int* __restrict__ done, const float* __restrict__ h0,
            const float* __restrict__ c0, const float* __restrict__ Whh,
            float* __restrict__ out)
{
    extern __shared__ char lsm[];
    float* whh_s = (float*)lsm;                 // [128][132] padded rows
    float* xw_s  = whh_s + 128 * 132;           // [64][128]
    float* hbuf  = xw_s + TSTEPS * 128;         // [2][128] (DSMEM target)
    float* hm    = hbuf + 256;                  // [128] masked h
    float* gate  = hm + 128;                    // [128] = [gate w][unit ul]
    float* m_all = gate + 128;                  // [64]

    const int t = threadIdx.x;
    const int b = blockIdx.x >> 2;
    const int rank = blockIdx.x & 3;
    const int w = t >> 5, ul = t & 31;
    const int G = w * HID + rank * 32 + ul;     // global gate-row

    // init: Whh row, all xw steps, masks, h0, c0
#pragma unroll
    for (int j4 = 0; j4 < 128; j4 += 4)
        *(float4*)&whh_s[t * 132 + j4] = *(const float4*)&Whh[(size_t)G * HID + j4];
    for (int s = 0; s < TSTEPS; s++)
        xw_s[s * 128 + t] = g_xw[(size_t)(s * BBATCH + b) * 512 + G];
    if (t < TSTEPS) m_all[t] = 1.0f - (float)done[t * BBATCH + b];
    hbuf[t] = h0[b * HID + t];                  // buffer 0 = h_0 (full vector)
    float creg = 0.f;
    if (t < 32) creg = c0[b * HID + rank * 32 + t];
    __syncthreads();
    CLUSTER_SYNC();                             // peers' smem ready for DSMEM

    const uint32_t hb_local = smem_u32(hbuf);
    float h_last = 0.f;
    for (int step = 0; step < TSTEPS; step++) {
        const int p = step & 1;
        const float m = m_all[step];
        hm[t] = hbuf[p * 128 + t] * m;
        __syncthreads();

        // gate row: acc = xw + sum_j hm[j] * whh[G][j]   (j ascending)
        float acc = xw_s[step * 128 + t];
        const float* wr = &whh_s[t * 132];
#pragma unroll 8
        for (int j = 0; j < 128; j += 4) {
            float4 hv = *(const float4*)&hm[j];
            float4 wv = *(const float4*)&wr[j];
            acc += hv.x * wv.x;
            acc += hv.y * wv.y;
            acc += hv.z * wv.z;
            acc += hv.w * wv.w;
        }
        gate[t] = acc;
        __syncthreads();

        if (t < 32) {
            float iv = sigmoidf_(gate[t]);
            float fv = sigmoidf_(gate[32 + t]);
            float gv = tanhf(gate[64 + t]);
            float ov = sigmoidf_(gate[96 + t]);
            float cc = fv * (creg * m) + iv * gv;
            creg = cc;
            float hh = ov * tanhf(cc);
            h_last = hh;
            g_hs[(size_t)(step * BBATCH + b) * HID + rank * 32 + t] = hh;
            if (step + 1 < TSTEPS) {
                uint32_t la = hb_local + (uint32_t)(((p ^ 1) * 128 + rank * 32 + t) * 4);
#pragma unroll
                for (int r = 0; r < 4; r++)
                    st_cluster(mapa_addr(la, r), hh);
            }
        }
        if (step + 1 < TSTEPS) CLUSTER_SYNC();
    }
    if (t < 32) {
        out[12288 + b * HID + rank * 32 + t] = h_last;
        out[16384 + b * HID + rank * 32 + t] = creg;
    }
}

// ---------------- heads: logits (2048x5) + value (2048x1) ---------------
__global__ void heads_kernel(
    const float* __restrict__ Wp, const float* __restrict__ bp,
    const float* __restrict__ Wv, const float* __restrict__ bv,
    float* __restrict__ out)
{
    int row = blockIdx.x * 8 + threadIdx.y;
    int lane = threadIdx.x;
    const float* h = g_hs + (size_t)row * HID;
    float4 hv = *(const float4*)&h[lane * 4];
    float vals[4] = {hv.x, hv.y, hv.z, hv.w};
    float r[6];
#pragma unroll
    for (int a = 0; a < 5; a++) {
        float s = 0.f;
#pragma unroll
        for (int q = 0; q < 4; q++) s += vals[q] * __ldg(&Wp[(lane * 4 + q) * 5 + a]);
        r[a] = s;
    }
    {
        float s = 0.f;
#pragma unroll
        for (int q = 0; q < 4; q++) s += vals[q] * __ldg(&Wv[lane * 4 + q]);
        r[5] = s;
    }
#pragma unroll
    for (int a = 0; a < 6; a++)
#pragma unroll
        for (int off = 16; off > 0; off >>= 1)
            r[a] += __shfl_xor_sync(0xffffffffu, r[a], off);
    if (lane == 0) {
#pragma unroll
        for (int a = 0; a < 5; a++) out[(size_t)row * 5 + a] = r[a] + __ldg(&bp[a]);
        out[10240 + row] = r[5] + __ldg(&bv[0]);
    }
}

// ---------------- launch ----------------
extern "C" void kernel_launch(void* const* d_in, const int* in_sizes, int n_in,
                              void* d_out, int out_size)
{
    const float* image    = (const float*)d_in[0];
    const int*   position = (const int*)d_in[1];
    const int*   done     = (const int*)d_in[2];
    const float* h0       = (const float*)d_in[3];
    const float* c0       = (const float*)d_in[4];
    const float* W1  = (const float*)d_in[5];
    const float* b1  = (const float*)d_in[6];
    const float* W2  = (const float*)d_in[7];
    const float* b2  = (const float*)d_in[8];
    const float* W3  = (const float*)d_in[9];
    const float* b3  = (const float*)d_in[10];
    const float* Wfc = (const float*)d_in[11];
    const float* bfc = (const float*)d_in[12];
    const float* Wih = (const float*)d_in[13];
    const float* Whh = (const float*)d_in[14];
    const float* bih = (const float*)d_in[15];
    const float* bhh = (const float*)d_in[16];
    const float* Wp  = (const float*)d_in[17];
    const float* bp  = (const float*)d_in[18];
    const float* Wv  = (const float*)d_in[19];
    const float* bv  = (const float*)d_in[20];
    float* out = (float*)d_out;

    const int SM_C1 = 2 * (2 * 128 * 144 + 2 * 32 * 144) + 192 * 4 + 512;
    const int SM_C2 = 110592 + 512 * 4 + 512;
    const int SM_C3 = 110592 + 576 * 4 + 512;
    const int SM_FC = 110592;
    // lstm: whh 128*132 + xw 64*128 + hbuf 256 + hm 128 + gate 128 + m 64
    const int SM_LS = (128 * 132 + TSTEPS * 128 + 256 + 128 + 128 + 64) * 4;  // 103168
    cudaFuncSetAttribute(conv1m_kernel, cudaFuncAttributeMaxDynamicSharedMemorySize, SM_C1);
    cudaFuncSetAttribute(conv2m_kernel, cudaFuncAttributeMaxDynamicSharedMemorySize, SM_C2);
    cudaFuncSetAttribute(conv3m_kernel, cudaFuncAttributeMaxDynamicSharedMemorySize, SM_C3);
    cudaFuncSetAttribute(fcm_kernel,   cudaFuncAttributeMaxDynamicSharedMemorySize, SM_FC);
    cudaFuncSetAttribute(lstm_kernel,  cudaFuncAttributeMaxDynamicSharedMemorySize, SM_LS);

    init_kernel<<<1, 32>>>();
    imgsplit_kernel<<<2048, 256>>>(image);
    wsplit_c1_kernel<<<8, 256>>>(W1);
    conv1m_kernel<<<dim3(1, 819200 / 128), 256, SM_C1>>>(b1);
    wsplit_c2_kernel<<<32, 256>>>(W2);
    conv2m_kernel<<<dim3(1, 165888 / 128), 256, SM_C2>>>(b2);
    wsplit_c3_kernel<<<32, 256>>>(W3);
    conv3m_kernel<<<dim3(1, 100352 / 128), 256, SM_C3>>>(b3);
    wsplit_fc_kernel<<<512, 256>>>(Wfc);
    fcm_kernel<<<dim3(8, 2048 / 128), 256, SM_FC>>>(bfc);
    xw_kernel<<<dim3(8, 32), 256>>>(Wih, bih, bhh, position);
    lstm_kernel<<<128, 128, SM_LS>>>(done, h0, c0, Whh, out);
    heads_kernel<<<256, dim3(32, 8)>>>(Wp, bp, Wv, bv, out);
}